// round 1
// baseline (speedup 1.0000x reference)
#include <cuda_runtime.h>
#include <cstdint>
#include <cstddef>

// Problem sizes (fixed)
#define BB 32
#define SS 2048
#define HH 256
#define ZZ 64

#define INV_T   (0.0625f)   // 1/sqrt(256)
#define NEGINF  (-1e9f)

// ---------------- scratch (device globals; no allocations allowed) ----------
__device__ float g_q[(size_t)BB * SS * HH];      // 64 MB
__device__ float g_k[(size_t)BB * SS * HH];      // 64 MB
__device__ float g_v[(size_t)BB * SS * ZZ];      // 16 MB
__device__ float g_cmax[(size_t)BB * SS];
__device__ float g_csum[(size_t)BB * SS];
__device__ float g_att[(size_t)BB * SS * SS];    // 512 MB fallback if attn not in d_out

// ---------------- mask dtype detection (bool-as-byte vs int32) --------------
__device__ __forceinline__ bool mask_is_i32(const void* m) {
    const unsigned int* p = (const unsigned int*)m;
    unsigned int o = p[0] | p[1] | p[2] | p[3] | p[4] | p[5] | p[6] | p[7];
    return o <= 1u;   // int32 0/1 values OR to <=1; byte-packed 0/1 sets high bytes
}

// =================== K1: C[M,N] = A[M,K] @ W[K,N], 128x128x16 ================
// M=65536, N=256, K=256 (q and k projections)
__global__ __launch_bounds__(256) void proj_kernel(
    const float* __restrict__ A, const float* __restrict__ W,
    float* __restrict__ C, int M, int N, int K)
{
    __shared__ float As[16][128];
    __shared__ float Ws[16][128];
    const int t  = threadIdx.x;
    const int m0 = blockIdx.y * 128;
    const int n0 = blockIdx.x * 128;

    const int ar  = t >> 2;          // 0..63
    const int ac4 = (t & 3) * 4;     // 0,4,8,12
    const int wr  = t >> 4;          // 0..15
    const int wc  = (t & 15) * 4;    // 0..60

    float acc[8][8];
#pragma unroll
    for (int u = 0; u < 8; ++u)
#pragma unroll
        for (int v = 0; v < 8; ++v) acc[u][v] = 0.f;

    for (int k0 = 0; k0 < K; k0 += 16) {
        float4 a0 = *(const float4*)&A[(size_t)(m0 + ar)      * K + k0 + ac4];
        float4 a1 = *(const float4*)&A[(size_t)(m0 + ar + 64) * K + k0 + ac4];
        float4 w0 = *(const float4*)&W[(size_t)(k0 + wr) * N + n0 + wc];
        float4 w1 = *(const float4*)&W[(size_t)(k0 + wr) * N + n0 + wc + 64];

        As[ac4 + 0][ar] = a0.x; As[ac4 + 1][ar] = a0.y;
        As[ac4 + 2][ar] = a0.z; As[ac4 + 3][ar] = a0.w;
        As[ac4 + 0][ar + 64] = a1.x; As[ac4 + 1][ar + 64] = a1.y;
        As[ac4 + 2][ar + 64] = a1.z; As[ac4 + 3][ar + 64] = a1.w;
        *(float4*)&Ws[wr][wc]      = w0;
        *(float4*)&Ws[wr][wc + 64] = w1;
        __syncthreads();

        const int ty = t >> 4, tx = t & 15;
#pragma unroll
        for (int kk = 0; kk < 16; ++kk) {
            float a[8], b[8];
#pragma unroll
            for (int u = 0; u < 8; ++u) { a[u] = As[kk][ty * 8 + u]; b[u] = Ws[kk][tx * 8 + u]; }
#pragma unroll
            for (int u = 0; u < 8; ++u)
#pragma unroll
                for (int v = 0; v < 8; ++v) acc[u][v] += a[u] * b[v];
        }
        __syncthreads();
    }

    const int ty = t >> 4, tx = t & 15;
#pragma unroll
    for (int u = 0; u < 8; ++u) {
        const size_t row = (size_t)(m0 + ty * 8 + u);
#pragma unroll
        for (int v = 0; v < 8; v += 4) {
            float4 r;
            r.x = acc[u][v + 0]; r.y = acc[u][v + 1]; r.z = acc[u][v + 2]; r.w = acc[u][v + 3];
            *(float4*)&C[row * N + n0 + tx * 8 + v] = r;
        }
    }
}

// =================== K2: v = latent[BS,64] @ Wv[64,64] =======================
__global__ __launch_bounds__(256) void vproj_kernel(
    const float* __restrict__ X, const float* __restrict__ Wv, float* __restrict__ V)
{
    __shared__ float Ws[64 * 65];
    __shared__ float Xs[32 * 65];
    const int t  = threadIdx.x;
    const int r0 = blockIdx.x * 32;

#pragma unroll
    for (int u = 0; u < 16; ++u) {
        int idx = u * 256 + t; int r = idx >> 6, c = idx & 63;
        Ws[r * 65 + c] = Wv[idx];
    }
#pragma unroll
    for (int u = 0; u < 8; ++u) {
        int idx = u * 256 + t; int r = idx >> 6, c = idx & 63;
        Xs[r * 65 + c] = X[(size_t)(r0 + r) * 64 + c];
    }
    __syncthreads();

    const int row = t >> 3;
    const int c0  = (t & 7) * 8;
    float acc[8];
#pragma unroll
    for (int u = 0; u < 8; ++u) acc[u] = 0.f;
#pragma unroll 8
    for (int z = 0; z < 64; ++z) {
        float a = Xs[row * 65 + z];
#pragma unroll
        for (int u = 0; u < 8; ++u) acc[u] += a * Ws[z * 65 + c0 + u];
    }
#pragma unroll
    for (int u = 0; u < 8; ++u) V[(size_t)(r0 + row) * 64 + c0 + u] = acc[u];
}

// ====== K3: alignment[b,i,j] = mask[b,i] ? (q_i . k_j)/16 : -1e9 =============
// 128x128x16 tile; A = q[b], B = k[b], C = A @ B^T
__global__ __launch_bounds__(256) void align_kernel(
    const float* __restrict__ Q, const float* __restrict__ Kp,
    const void* __restrict__ mask, float* __restrict__ Cout)
{
    const int b = blockIdx.z;
    const float* A  = Q  + (size_t)b * SS * HH;
    const float* Bm = Kp + (size_t)b * SS * HH;
    float*       C  = Cout + (size_t)b * SS * SS;

    __shared__ float As[16][128];
    __shared__ float Bs[16][128];
    const int t  = threadIdx.x;
    const int m0 = blockIdx.y * 128;
    const int n0 = blockIdx.x * 128;

    const int ar  = t >> 2;
    const int ac4 = (t & 3) * 4;

    float acc[8][8];
#pragma unroll
    for (int u = 0; u < 8; ++u)
#pragma unroll
        for (int v = 0; v < 8; ++v) acc[u][v] = 0.f;

    for (int k0 = 0; k0 < HH; k0 += 16) {
        float4 a0 = *(const float4*)&A [(size_t)(m0 + ar)      * HH + k0 + ac4];
        float4 a1 = *(const float4*)&A [(size_t)(m0 + ar + 64) * HH + k0 + ac4];
        float4 b0 = *(const float4*)&Bm[(size_t)(n0 + ar)      * HH + k0 + ac4];
        float4 b1 = *(const float4*)&Bm[(size_t)(n0 + ar + 64) * HH + k0 + ac4];

        As[ac4 + 0][ar] = a0.x; As[ac4 + 1][ar] = a0.y;
        As[ac4 + 2][ar] = a0.z; As[ac4 + 3][ar] = a0.w;
        As[ac4 + 0][ar + 64] = a1.x; As[ac4 + 1][ar + 64] = a1.y;
        As[ac4 + 2][ar + 64] = a1.z; As[ac4 + 3][ar + 64] = a1.w;
        Bs[ac4 + 0][ar] = b0.x; Bs[ac4 + 1][ar] = b0.y;
        Bs[ac4 + 2][ar] = b0.z; Bs[ac4 + 3][ar] = b0.w;
        Bs[ac4 + 0][ar + 64] = b1.x; Bs[ac4 + 1][ar + 64] = b1.y;
        Bs[ac4 + 2][ar + 64] = b1.z; Bs[ac4 + 3][ar + 64] = b1.w;
        __syncthreads();

        const int ty = t >> 4, tx = t & 15;
#pragma unroll
        for (int kk = 0; kk < 16; ++kk) {
            float a[8], bb[8];
#pragma unroll
            for (int u = 0; u < 8; ++u) { a[u] = As[kk][ty * 8 + u]; bb[u] = Bs[kk][tx * 8 + u]; }
#pragma unroll
            for (int u = 0; u < 8; ++u)
#pragma unroll
                for (int v = 0; v < 8; ++v) acc[u][v] += a[u] * bb[v];
        }
        __syncthreads();
    }

    const bool i32 = mask_is_i32(mask);
    const int*           mi = (const int*)mask;
    const unsigned char* mb = (const unsigned char*)mask;
    const int ty = t >> 4, tx = t & 15;
#pragma unroll
    for (int u = 0; u < 8; ++u) {
        const int i = m0 + ty * 8 + u;
        const bool keep = i32 ? (mi[b * SS + i] != 0) : (mb[b * SS + i] != 0);
        const size_t rowoff = (size_t)i * SS + n0 + tx * 8;
#pragma unroll
        for (int v = 0; v < 8; v += 4) {
            float4 r;
            r.x = keep ? acc[u][v + 0] * INV_T : NEGINF;
            r.y = keep ? acc[u][v + 1] * INV_T : NEGINF;
            r.z = keep ? acc[u][v + 2] * INV_T : NEGINF;
            r.w = keep ? acc[u][v + 3] * INV_T : NEGINF;
            *(float4*)&C[rowoff + v] = r;
        }
    }
}

// ===== K4: per-column (axis i) online softmax stats: max & sum of exp =======
__global__ __launch_bounds__(256) void colstats_kernel(
    const float* __restrict__ att, float* __restrict__ cmax, float* __restrict__ csum)
{
    const int b = blockIdx.y;
    const int j = blockIdx.x * 256 + threadIdx.x;
    const float* base = att + (size_t)b * SS * SS + j;

    float m = -3.4e38f, s = 0.f;
#pragma unroll 4
    for (int i = 0; i < SS; ++i) {
        float v = base[(size_t)i * SS];
        if (v > m) { s = s * __expf(m - v) + 1.0f; m = v; }
        else       { s += __expf(v - m); }
    }
    cmax[b * SS + j] = m;
    csum[b * SS + j] = s;
}

// ===== K5: normalize attn in place + output = attn @ v =======================
// CTA: one (batch, 64-row i-tile); loops over 32 j-tiles of 64.
__global__ __launch_bounds__(256) void fused_out_kernel(
    float* __restrict__ att, const float* __restrict__ V,
    const float* __restrict__ cmax, const float* __restrict__ csum,
    float* __restrict__ Out)
{
    __shared__ float attnS[64 * 65];
    __shared__ float vS[64 * 65];
    __shared__ float cmaxS[64];
    __shared__ float rcsS[64];

    const int t  = threadIdx.x;
    const int b  = blockIdx.y;
    const int i0 = blockIdx.x * 64;

    float* attB = att + (size_t)b * SS * SS;
    const float* vB = V + (size_t)b * SS * ZZ;

    const int ty = t >> 4, tx = t & 15;    // rows ty*4.., cols tx*4..
    float acc[4][4];
#pragma unroll
    for (int u = 0; u < 4; ++u)
#pragma unroll
        for (int v = 0; v < 4; ++v) acc[u][v] = 0.f;

    for (int jt = 0; jt < 32; ++jt) {
        const int j0 = jt * 64;
        __syncthreads();   // previous tile's compute done before overwrite
        if (t < 64)        cmaxS[t] = cmax[b * SS + j0 + t];
        else if (t < 128)  rcsS[t - 64] = 1.0f / csum[b * SS + j0 + t - 64];
        __syncthreads();

        // normalize 64x64 tile: write attn to gmem (in place) + stage in smem
#pragma unroll
        for (int u = 0; u < 16; ++u) {
            int idx = u * 256 + t; int r = idx >> 6, c = idx & 63;
            size_t g = (size_t)(i0 + r) * SS + j0 + c;
            float raw = attB[g];
            float e = __expf(raw - cmaxS[c]) * rcsS[c];
            attB[g] = e;
            attnS[r * 65 + c] = e;
        }
#pragma unroll
        for (int u = 0; u < 16; ++u) {
            int idx = u * 256 + t; int r = idx >> 6, c = idx & 63;
            vS[r * 65 + c] = vB[(size_t)(j0 + r) * ZZ + c];
        }
        __syncthreads();

#pragma unroll 8
        for (int jj = 0; jj < 64; ++jj) {
            float a[4], bv[4];
#pragma unroll
            for (int u = 0; u < 4; ++u) a[u]  = attnS[(ty * 4 + u) * 65 + jj];
#pragma unroll
            for (int v = 0; v < 4; ++v) bv[v] = vS[jj * 65 + tx * 4 + v];
#pragma unroll
            for (int u = 0; u < 4; ++u)
#pragma unroll
                for (int v = 0; v < 4; ++v) acc[u][v] += a[u] * bv[v];
        }
    }

#pragma unroll
    for (int u = 0; u < 4; ++u) {
        size_t row = (size_t)b * SS + i0 + ty * 4 + u;
#pragma unroll
        for (int v = 0; v < 4; ++v)
            Out[row * ZZ + tx * 4 + v] = acc[u][v];
    }
}

// ============================== launch ======================================
extern "C" void kernel_launch(void* const* d_in, const int* in_sizes, int n_in,
                              void* d_out, int out_size)
{
    const float* enc  = (const float*)d_in[0];   // encoder_hidden_states [B,S,H]
    const float* dec  = (const float*)d_in[1];   // decoder_hidden_states [B,S,H]
    /* d_in[2]: decoder_final_hidden_state — unused by reference */
    const float* lat  = (const float*)d_in[3];   // latent_z_seq [B,S,Z]
    const void*  mask = d_in[4];                 // mask [B,S] (bool or int32)
    const float* Wq   = (const float*)d_in[5];
    const float* Wk   = (const float*)d_in[6];
    const float* Wv   = (const float*)d_in[7];

    float* outp = (float*)d_out;

    const size_t OUTE = (size_t)BB * SS * ZZ;        // 4,194,304
    const size_t ATTE = (size_t)BB * SS * SS;        // 134,217,728

    float *qp, *kp, *vp, *cmaxp, *csump, *attfb;
    cudaGetSymbolAddress((void**)&qp,    g_q);
    cudaGetSymbolAddress((void**)&kp,    g_k);
    cudaGetSymbolAddress((void**)&vp,    g_v);
    cudaGetSymbolAddress((void**)&cmaxp, g_cmax);
    cudaGetSymbolAddress((void**)&csump, g_csum);
    cudaGetSymbolAddress((void**)&attfb, g_att);

    // attn lives in d_out right after output if there is room, else scratch
    float* attnbuf = ((size_t)out_size >= OUTE + ATTE) ? (outp + OUTE) : attfb;

    const int M = BB * SS;   // 65536

    dim3 gProj(HH / 128, M / 128);                 // (2, 512)
    proj_kernel<<<gProj, 256>>>(dec, Wq, qp, M, HH, HH);
    proj_kernel<<<gProj, 256>>>(enc, Wk, kp, M, HH, HH);
    vproj_kernel<<<M / 32, 256>>>(lat, Wv, vp);

    dim3 gAlign(SS / 128, SS / 128, BB);           // (16, 16, 32)
    align_kernel<<<gAlign, 256>>>(qp, kp, mask, attnbuf);

    dim3 gStats(SS / 256, BB);                     // (8, 32)
    colstats_kernel<<<gStats, 256>>>(attnbuf, cmaxp, csump);

    dim3 gOut(SS / 64, BB);                        // (32, 32)
    fused_out_kernel<<<gOut, 256>>>(attnbuf, vp, cmaxp, csump, outp);
}

// round 3
// speedup vs baseline: 1.3778x; 1.3778x over previous
#include <cuda_runtime.h>
#include <cuda_fp16.h>
#include <cstdint>
#include <cstddef>

// Problem sizes (fixed)
#define BB 32
#define SS 2048
#define HH 256
#define ZZ 64

#define INV_T   (0.0625f)   // 1/sqrt(256)
#define NEGINF  (-1e9f)

// ---------------- scratch (device globals; no allocations allowed) ----------
__device__ float  g_GT[HH * HH];                      // GT[h'][h] = (Wq Wk^T)^T
__device__ __half g_GThi[HH * HH];
__device__ __half g_GTlo[HH * HH];
__device__ __half g_dechi[(size_t)BB * SS * HH];      // 32 MB
__device__ __half g_declo[(size_t)BB * SS * HH];
__device__ __half g_ehi[(size_t)BB * SS * HH];
__device__ __half g_elo[(size_t)BB * SS * HH];
__device__ __half g_qhi[(size_t)BB * SS * HH];        // q' split
__device__ __half g_qlo[(size_t)BB * SS * HH];
__device__ float  g_v[(size_t)BB * SS * ZZ];          // 16 MB
__device__ float  g_cmax[(size_t)BB * SS];
__device__ float  g_csum[(size_t)BB * SS];
__device__ float  g_att[(size_t)BB * SS * SS];        // 512 MB fallback

// ---------------- mask dtype detection (bool-as-byte vs int32) --------------
__device__ __forceinline__ bool mask_is_i32(const void* m) {
    const unsigned int* p = (const unsigned int*)m;
    unsigned int o = p[0] | p[1] | p[2] | p[3] | p[4] | p[5] | p[6] | p[7];
    return o <= 1u;
}

__device__ __forceinline__ uint32_t smem_u32(const void* p) {
    uint32_t a;
    asm("{ .reg .u64 t; cvta.to.shared.u64 t, %1; cvt.u32.u64 %0, t; }" : "=r"(a) : "l"(p));
    return a;
}

__device__ __forceinline__ void hmma16816(float* d, const uint32_t* a, const uint32_t* b) {
    asm volatile(
        "mma.sync.aligned.m16n8k16.row.col.f32.f16.f16.f32 "
        "{%0,%1,%2,%3}, {%4,%5,%6,%7}, {%8,%9}, {%0,%1,%2,%3};"
        : "+f"(d[0]), "+f"(d[1]), "+f"(d[2]), "+f"(d[3])
        : "r"(a[0]), "r"(a[1]), "r"(a[2]), "r"(a[3]), "r"(b[0]), "r"(b[1]));
}

// =================== K0: O[r][c] = sum_k A[r,k] * B[c,k]  (256x256x256) ======
__global__ __launch_bounds__(256) void gmat_kernel(
    const float* __restrict__ A, const float* __restrict__ B, float* __restrict__ O)
{
    __shared__ float aS[32 * 65];
    __shared__ float bS[32 * 65];
    const int t  = threadIdx.x;
    const int r0 = blockIdx.y * 64;
    const int c0 = blockIdx.x * 64;

    const int lr = t >> 2;
    const int lc = (t & 3) * 8;

    float acc[4][4];
#pragma unroll
    for (int u = 0; u < 4; ++u)
#pragma unroll
        for (int v = 0; v < 4; ++v) acc[u][v] = 0.f;

    for (int k0 = 0; k0 < HH; k0 += 32) {
        __syncthreads();
        float4 a0 = *(const float4*)&A[(size_t)(r0 + lr) * HH + k0 + lc];
        float4 a1 = *(const float4*)&A[(size_t)(r0 + lr) * HH + k0 + lc + 4];
        float4 b0 = *(const float4*)&B[(size_t)(c0 + lr) * HH + k0 + lc];
        float4 b1 = *(const float4*)&B[(size_t)(c0 + lr) * HH + k0 + lc + 4];
        aS[(lc + 0) * 65 + lr] = a0.x; aS[(lc + 1) * 65 + lr] = a0.y;
        aS[(lc + 2) * 65 + lr] = a0.z; aS[(lc + 3) * 65 + lr] = a0.w;
        aS[(lc + 4) * 65 + lr] = a1.x; aS[(lc + 5) * 65 + lr] = a1.y;
        aS[(lc + 6) * 65 + lr] = a1.z; aS[(lc + 7) * 65 + lr] = a1.w;
        bS[(lc + 0) * 65 + lr] = b0.x; bS[(lc + 1) * 65 + lr] = b0.y;
        bS[(lc + 2) * 65 + lr] = b0.z; bS[(lc + 3) * 65 + lr] = b0.w;
        bS[(lc + 4) * 65 + lr] = b1.x; bS[(lc + 5) * 65 + lr] = b1.y;
        bS[(lc + 6) * 65 + lr] = b1.z; bS[(lc + 7) * 65 + lr] = b1.w;
        __syncthreads();

        const int ty = t >> 4, tx = t & 15;
#pragma unroll
        for (int kk = 0; kk < 32; ++kk) {
            float a[4], bb[4];
#pragma unroll
            for (int u = 0; u < 4; ++u) { a[u] = aS[kk * 65 + ty * 4 + u]; bb[u] = bS[kk * 65 + tx * 4 + u]; }
#pragma unroll
            for (int u = 0; u < 4; ++u)
#pragma unroll
                for (int v = 0; v < 4; ++v) acc[u][v] += a[u] * bb[v];
        }
    }

    const int ty = t >> 4, tx = t & 15;
#pragma unroll
    for (int u = 0; u < 4; ++u) {
        float4 r;
        r.x = acc[u][0]; r.y = acc[u][1]; r.z = acc[u][2]; r.w = acc[u][3];
        *(float4*)&O[(size_t)(r0 + ty * 4 + u) * HH + c0 + tx * 4] = r;
    }
}

// ============ split fp32 -> fp16 hi + fp16 lo (elementwise) ==================
__global__ __launch_bounds__(256) void split_kernel(
    const float* __restrict__ in, __half* __restrict__ hi, __half* __restrict__ lo, int n4)
{
    int i = blockIdx.x * 256 + threadIdx.x;
    int stride = gridDim.x * 256;
    for (; i < n4; i += stride) {
        float4 x = ((const float4*)in)[i];
        __half hx = __float2half_rn(x.x), hy = __float2half_rn(x.y);
        __half hz = __float2half_rn(x.z), hw = __float2half_rn(x.w);
        __half lx = __float2half_rn(x.x - __half2float(hx));
        __half ly = __float2half_rn(x.y - __half2float(hy));
        __half lz = __float2half_rn(x.z - __half2float(hz));
        __half lw = __float2half_rn(x.w - __half2float(hw));
        ((__half2*)hi)[i * 2 + 0] = __halves2half2(hx, hy);
        ((__half2*)hi)[i * 2 + 1] = __halves2half2(hz, hw);
        ((__half2*)lo)[i * 2 + 0] = __halves2half2(lx, ly);
        ((__half2*)lo)[i * 2 + 1] = __halves2half2(lz, lw);
    }
}

// =================== K2: v = latent[BS,64] @ Wv[64,64] =======================
__global__ __launch_bounds__(256) void vproj_kernel(
    const float* __restrict__ X, const float* __restrict__ Wv, float* __restrict__ V)
{
    __shared__ float Ws[64 * 65];
    __shared__ float Xs[32 * 65];
    const int t  = threadIdx.x;
    const int r0 = blockIdx.x * 32;

#pragma unroll
    for (int u = 0; u < 16; ++u) {
        int idx = u * 256 + t; int r = idx >> 6, c = idx & 63;
        Ws[r * 65 + c] = Wv[idx];
    }
#pragma unroll
    for (int u = 0; u < 8; ++u) {
        int idx = u * 256 + t; int r = idx >> 6, c = idx & 63;
        Xs[r * 65 + c] = X[(size_t)(r0 + r) * 64 + c];
    }
    __syncthreads();

    const int row = t >> 3;
    const int c0  = (t & 7) * 8;
    float acc[8];
#pragma unroll
    for (int u = 0; u < 8; ++u) acc[u] = 0.f;
#pragma unroll 8
    for (int z = 0; z < 64; ++z) {
        float a = Xs[row * 65 + z];
#pragma unroll
        for (int u = 0; u < 8; ++u) acc[u] += a * Ws[z * 65 + c0 + u];
    }
#pragma unroll
    for (int u = 0; u < 8; ++u) V[(size_t)(r0 + row) * 64 + c0 + u] = acc[u];
}

// =========== Split-precision HMMA GEMM: C = A @ B^T, K=256 ===================
// A: [*, 256] fp16 hi/lo rows, B: [*, 256] fp16 hi/lo rows (both k-contiguous).
// CTA tile 128x128, 8 warps (2x4), warp tile 64x32, k-chunk 32, double buffer.
// IS_ALIGN=1: C[b,i,j] = mask(i) ? acc/16 : -1e9  into att[b]
// IS_ALIGN=0: write split fp16 (qhi,qlo) of acc
template<bool IS_ALIGN>
__global__ void __launch_bounds__(256) mma_split_kernel(
    const __half* __restrict__ Ahig, const __half* __restrict__ Alog,
    const __half* __restrict__ Bhig, const __half* __restrict__ Blog,
    const void* __restrict__ mask, float* __restrict__ Cout,
    __half* __restrict__ Qhi, __half* __restrict__ Qlo)
{
    extern __shared__ __half sm[];
    const int t    = threadIdx.x;
    const int lane = t & 31;
    const int wid  = t >> 5;
    const int warpM = wid >> 2;     // 0..1
    const int warpN = wid & 3;      // 0..3
    const int b  = IS_ALIGN ? blockIdx.z : 0;
    const int m0 = blockIdx.y * 128;
    const int n0 = blockIdx.x * 128;

    const size_t arow = IS_ALIGN ? ((size_t)b * SS + m0) : (size_t)m0;
    const size_t brow = IS_ALIGN ? ((size_t)b * SS + n0) : (size_t)n0;
    const __half* Ah = Ahig + arow * HH;
    const __half* Al = Alog + arow * HH;
    const __half* Bh = Bhig + brow * HH;
    const __half* Bl = Blog + brow * HH;

    const uint32_t smbase = smem_u32(sm);

    // smem layout per buffer p (halves): AHI +0, ALO +5120, BHI +10240, BLO +15360
    // row stride 40 halves (conflict-free for 32-bit frag loads)

    float acc[4][4][4];
#pragma unroll
    for (int mt = 0; mt < 4; ++mt)
#pragma unroll
        for (int nt = 0; nt < 4; ++nt)
#pragma unroll
            for (int r = 0; r < 4; ++r) acc[mt][nt][r] = 0.f;

    auto issue = [&](int chunk, int p) {
#pragma unroll
        for (int i = 0; i < 8; ++i) {
            const __half* basep = (i < 2) ? Ah : (i < 4) ? Al : (i < 6) ? Bh : Bl;
            const int tile = i >> 1;
            const int flat = i * 256 + t;
            const int w = flat & 511;
            const int r = w >> 2, c16 = w & 3;
            const __half* g = basep + (size_t)r * HH + chunk * 32 + c16 * 8;
            const uint32_t d = smbase +
                (uint32_t)((p * 20480 + tile * 5120 + r * 40 + c16 * 8) * 2);
            asm volatile("cp.async.cg.shared.global [%0], [%1], 16;" :: "r"(d), "l"(g));
        }
        asm volatile("cp.async.commit_group;" ::: "memory");
    };

    issue(0, 0);

    for (int c = 0; c < 8; ++c) {
        asm volatile("cp.async.wait_group 0;" ::: "memory");
        __syncthreads();
        if (c < 7) issue(c + 1, (c + 1) & 1);

        const int p = c & 1;
        const int abase  = p * 20480;
        const int albase = abase + 5120;
        const int bbase  = abase + 10240;
        const int blbase = abase + 15360;

#pragma unroll
        for (int k16 = 0; k16 < 32; k16 += 16) {
            const int cc = k16 + (lane & 3) * 2;
            uint32_t ah[4][4], al[4][4], bh[4][2], bl[4][2];
#pragma unroll
            for (int mt = 0; mt < 4; ++mt) {
                const int r = warpM * 64 + mt * 16 + (lane >> 2);
                ah[mt][0] = *(const uint32_t*)&sm[abase  + r * 40 + cc];
                ah[mt][1] = *(const uint32_t*)&sm[abase  + (r + 8) * 40 + cc];
                ah[mt][2] = *(const uint32_t*)&sm[abase  + r * 40 + cc + 8];
                ah[mt][3] = *(const uint32_t*)&sm[abase  + (r + 8) * 40 + cc + 8];
                al[mt][0] = *(const uint32_t*)&sm[albase + r * 40 + cc];
                al[mt][1] = *(const uint32_t*)&sm[albase + (r + 8) * 40 + cc];
                al[mt][2] = *(const uint32_t*)&sm[albase + r * 40 + cc + 8];
                al[mt][3] = *(const uint32_t*)&sm[albase + (r + 8) * 40 + cc + 8];
            }
#pragma unroll
            for (int nt = 0; nt < 4; ++nt) {
                const int n = warpN * 32 + nt * 8 + (lane >> 2);
                bh[nt][0] = *(const uint32_t*)&sm[bbase  + n * 40 + cc];
                bh[nt][1] = *(const uint32_t*)&sm[bbase  + n * 40 + cc + 8];
                bl[nt][0] = *(const uint32_t*)&sm[blbase + n * 40 + cc];
                bl[nt][1] = *(const uint32_t*)&sm[blbase + n * 40 + cc + 8];
            }
#pragma unroll
            for (int mt = 0; mt < 4; ++mt)
#pragma unroll
                for (int nt = 0; nt < 4; ++nt) {
                    hmma16816(acc[mt][nt], ah[mt], bh[nt]);
                    hmma16816(acc[mt][nt], ah[mt], bl[nt]);
                    hmma16816(acc[mt][nt], al[mt], bh[nt]);
                }
        }
    }

    // ----------------------------- epilogue ---------------------------------
    if (IS_ALIGN) {
        const bool i32 = mask_is_i32(mask);
        const int*           mi = (const int*)mask;
        const unsigned char* mb = (const unsigned char*)mask;
#pragma unroll
        for (int mt = 0; mt < 4; ++mt) {
            const int i = m0 + warpM * 64 + mt * 16 + (lane >> 2);
            const bool k0 = i32 ? (mi[b * SS + i] != 0)     : (mb[b * SS + i] != 0);
            const bool k8 = i32 ? (mi[b * SS + i + 8] != 0) : (mb[b * SS + i + 8] != 0);
            float* row0 = Cout + ((size_t)b * SS + i) * SS;
            float* row8 = row0 + (size_t)8 * SS;
#pragma unroll
            for (int nt = 0; nt < 4; ++nt) {
                const int j = n0 + warpN * 32 + nt * 8 + (lane & 3) * 2;
                float2 v0, v8;
                v0.x = k0 ? acc[mt][nt][0] * INV_T : NEGINF;
                v0.y = k0 ? acc[mt][nt][1] * INV_T : NEGINF;
                v8.x = k8 ? acc[mt][nt][2] * INV_T : NEGINF;
                v8.y = k8 ? acc[mt][nt][3] * INV_T : NEGINF;
                *(float2*)&row0[j] = v0;
                *(float2*)&row8[j] = v8;
            }
        }
    } else {
#pragma unroll
        for (int mt = 0; mt < 4; ++mt) {
            const size_t i = (size_t)m0 + warpM * 64 + mt * 16 + (lane >> 2);
#pragma unroll
            for (int nt = 0; nt < 4; ++nt) {
                const int n = n0 + warpN * 32 + nt * 8 + (lane & 3) * 2;
#pragma unroll
                for (int half = 0; half < 2; ++half) {
                    const size_t row = i + half * 8;
                    float x0 = acc[mt][nt][half * 2 + 0];
                    float x1 = acc[mt][nt][half * 2 + 1];
                    __half h0 = __float2half_rn(x0), h1 = __float2half_rn(x1);
                    __half l0 = __float2half_rn(x0 - __half2float(h0));
                    __half l1 = __float2half_rn(x1 - __half2float(h1));
                    *(__half2*)&Qhi[row * HH + n] = __halves2half2(h0, h1);
                    *(__half2*)&Qlo[row * HH + n] = __halves2half2(l0, l1);
                }
            }
        }
    }
}

// ===== K4: per-column (axis i) online softmax stats: max & sum of exp =======
__global__ __launch_bounds__(256) void colstats_kernel(
    const float* __restrict__ att, float* __restrict__ cmax, float* __restrict__ csum)
{
    const int b = blockIdx.y;
    const int j = blockIdx.x * 256 + threadIdx.x;
    const float* base = att + (size_t)b * SS * SS + j;

    float m = -3.4e38f, s = 0.f;
#pragma unroll 4
    for (int i = 0; i < SS; ++i) {
        float v = base[(size_t)i * SS];
        if (v > m) { s = s * __expf(m - v) + 1.0f; m = v; }
        else       { s += __expf(v - m); }
    }
    cmax[b * SS + j] = m;
    csum[b * SS + j] = s;
}

// ===== K5: normalize attn in place + output = attn @ v =======================
__global__ __launch_bounds__(256) void fused_out_kernel(
    float* __restrict__ att, const float* __restrict__ V,
    const float* __restrict__ cmax, const float* __restrict__ csum,
    float* __restrict__ Out)
{
    __shared__ float attnS[64 * 65];
    __shared__ float vS[64 * 65];
    __shared__ float cmaxS[64];
    __shared__ float rcsS[64];

    const int t  = threadIdx.x;
    const int b  = blockIdx.y;
    const int i0 = blockIdx.x * 64;

    float* attB = att + (size_t)b * SS * SS;
    const float* vB = V + (size_t)b * SS * ZZ;

    const int ty = t >> 4, tx = t & 15;
    float acc[4][4];
#pragma unroll
    for (int u = 0; u < 4; ++u)
#pragma unroll
        for (int v = 0; v < 4; ++v) acc[u][v] = 0.f;

    for (int jt = 0; jt < 32; ++jt) {
        const int j0 = jt * 64;
        __syncthreads();
        if (t < 64)        cmaxS[t] = cmax[b * SS + j0 + t];
        else if (t < 128)  rcsS[t - 64] = 1.0f / csum[b * SS + j0 + t - 64];
        __syncthreads();

#pragma unroll
        for (int u = 0; u < 16; ++u) {
            int idx = u * 256 + t; int r = idx >> 6, c = idx & 63;
            size_t g = (size_t)(i0 + r) * SS + j0 + c;
            float raw = attB[g];
            float e = __expf(raw - cmaxS[c]) * rcsS[c];
            attB[g] = e;
            attnS[r * 65 + c] = e;
        }
#pragma unroll
        for (int u = 0; u < 16; ++u) {
            int idx = u * 256 + t; int r = idx >> 6, c = idx & 63;
            vS[r * 65 + c] = vB[(size_t)(j0 + r) * ZZ + c];
        }
        __syncthreads();

#pragma unroll 8
        for (int jj = 0; jj < 64; ++jj) {
            float a[4], bv[4];
#pragma unroll
            for (int u = 0; u < 4; ++u) a[u]  = attnS[(ty * 4 + u) * 65 + jj];
#pragma unroll
            for (int v = 0; v < 4; ++v) bv[v] = vS[jj * 65 + tx * 4 + v];
#pragma unroll
            for (int u = 0; u < 4; ++u)
#pragma unroll
                for (int v = 0; v < 4; ++v) acc[u][v] += a[u] * bv[v];
        }
    }

#pragma unroll
    for (int u = 0; u < 4; ++u) {
        size_t row = (size_t)b * SS + i0 + ty * 4 + u;
#pragma unroll
        for (int v = 0; v < 4; ++v)
            Out[row * ZZ + tx * 4 + v] = acc[u][v];
    }
}

// ============================== launch ======================================
extern "C" void kernel_launch(void* const* d_in, const int* in_sizes, int n_in,
                              void* d_out, int out_size)
{
    const float* enc  = (const float*)d_in[0];
    const float* dec  = (const float*)d_in[1];
    const float* lat  = (const float*)d_in[3];
    const void*  mask = d_in[4];
    const float* Wq   = (const float*)d_in[5];
    const float* Wk   = (const float*)d_in[6];
    const float* Wv   = (const float*)d_in[7];

    float* outp = (float*)d_out;

    const size_t OUTE = (size_t)BB * SS * ZZ;
    const size_t ATTE = (size_t)BB * SS * SS;

    float  *GTp, *vp, *cmaxp, *csump, *attfb;
    __half *GThi, *GTlo, *dhi, *dlo, *ehi, *elo, *qhi, *qlo;
    cudaGetSymbolAddress((void**)&GTp,   g_GT);
    cudaGetSymbolAddress((void**)&GThi,  g_GThi);
    cudaGetSymbolAddress((void**)&GTlo,  g_GTlo);
    cudaGetSymbolAddress((void**)&dhi,   g_dechi);
    cudaGetSymbolAddress((void**)&dlo,   g_declo);
    cudaGetSymbolAddress((void**)&ehi,   g_ehi);
    cudaGetSymbolAddress((void**)&elo,   g_elo);
    cudaGetSymbolAddress((void**)&qhi,   g_qhi);
    cudaGetSymbolAddress((void**)&qlo,   g_qlo);
    cudaGetSymbolAddress((void**)&vp,    g_v);
    cudaGetSymbolAddress((void**)&cmaxp, g_cmax);
    cudaGetSymbolAddress((void**)&csump, g_csum);
    cudaGetSymbolAddress((void**)&attfb, g_att);

    float* attnbuf = ((size_t)out_size >= OUTE + ATTE) ? (outp + OUTE) : attfb;

    const int M = BB * SS;   // 65536

    static int smem_set = 0;
    if (!smem_set) {
        cudaFuncSetAttribute(mma_split_kernel<true>,
                             cudaFuncAttributeMaxDynamicSharedMemorySize, 81920);
        cudaFuncSetAttribute(mma_split_kernel<false>,
                             cudaFuncAttributeMaxDynamicSharedMemorySize, 81920);
        smem_set = 1;
    }

    // GT[h'][h] = sum_d Wk[h',d] * Wq[h,d]   (= (Wq Wk^T)^T)
    gmat_kernel<<<dim3(4, 4), 256>>>(Wk, Wq, GTp);
    split_kernel<<<64, 256>>>(GTp, GThi, GTlo, HH * HH / 4);
    split_kernel<<<592, 256>>>(dec, dhi, dlo, M * HH / 4);
    split_kernel<<<592, 256>>>(enc, ehi, elo, M * HH / 4);
    vproj_kernel<<<M / 32, 256>>>(lat, Wv, vp);

    // q' = dec @ GT^T  (split-precision HMMA), output split fp16
    mma_split_kernel<false><<<dim3(HH / 128, M / 128, 1), 256, 81920>>>(
        dhi, dlo, GThi, GTlo, nullptr, nullptr, qhi, qlo);

    // alignment = (q' @ enc^T)/16 with query-row masking (split HMMA)
    mma_split_kernel<true><<<dim3(SS / 128, SS / 128, BB), 256, 81920>>>(
        qhi, qlo, ehi, elo, mask, attnbuf, nullptr, nullptr);

    colstats_kernel<<<dim3(SS / 256, BB), 256>>>(attnbuf, cmaxp, csump);
    fused_out_kernel<<<dim3(SS / 64, BB), 256>>>(attnbuf, vp, cmaxp, csump, outp);
}

// round 4
// speedup vs baseline: 2.6724x; 1.9396x over previous
#include <cuda_runtime.h>
#include <cuda_fp16.h>
#include <cstdint>
#include <cstddef>

// Problem sizes (fixed)
#define BB 32
#define SS 2048
#define HH 256
#define ZZ 64

#define INV_T   (0.0625f)   // 1/sqrt(256)
#define NEGINF  (-1e9f)

// ---------------- scratch (device globals; no allocations allowed) ----------
__device__ float  g_GT[HH * HH];
__device__ __half g_GThi[HH * HH];
__device__ __half g_GTlo[HH * HH];
__device__ __half g_dechi[(size_t)BB * SS * HH];
__device__ __half g_declo[(size_t)BB * SS * HH];
__device__ __half g_ehi[(size_t)BB * SS * HH];
__device__ __half g_elo[(size_t)BB * SS * HH];
__device__ __half g_qhi[(size_t)BB * SS * HH];
__device__ __half g_qlo[(size_t)BB * SS * HH];
__device__ float  g_v[(size_t)BB * SS * ZZ];
__device__ float  g_pmax[(size_t)BB * 16 * SS];   // per-i-tile column max
__device__ float  g_psum[(size_t)BB * 16 * SS];   // per-i-tile column sum
__device__ float  g_cmax[(size_t)BB * SS];
__device__ float  g_rcs[(size_t)BB * SS];         // reciprocal column sum
__device__ float  g_att[(size_t)BB * SS * SS];    // fallback attn buffer

// ---------------- mask dtype detection --------------------------------------
__device__ __forceinline__ bool mask_is_i32(const void* m) {
    const unsigned int* p = (const unsigned int*)m;
    unsigned int o = p[0] | p[1] | p[2] | p[3] | p[4] | p[5] | p[6] | p[7];
    return o <= 1u;
}

__device__ __forceinline__ uint32_t smem_u32(const void* p) {
    uint32_t a;
    asm("{ .reg .u64 t; cvta.to.shared.u64 t, %1; cvt.u32.u64 %0, t; }" : "=r"(a) : "l"(p));
    return a;
}

// FMA-pipe exp (no MUFU): exp(x) = 2^(x*log2e), poly on [-0.5,0.5], rel err ~2e-6
__device__ __forceinline__ float fexp(float x) {
    float y = fmaxf(x * 1.4426950408889634f, -126.0f);
    float r = rintf(y);
    float f = y - r;
    float p =              1.3333558146e-3f;
    p = fmaf(p, f, 9.6181291077e-3f);
    p = fmaf(p, f, 5.5504108664e-2f);
    p = fmaf(p, f, 2.4022650696e-1f);
    p = fmaf(p, f, 6.9314718056e-1f);
    p = fmaf(p, f, 1.0f);
    return __int_as_float(__float_as_int(p) + (((int)r) << 23));
}

__device__ __forceinline__ void hmma16816(float* d, const uint32_t* a, const uint32_t* b) {
    asm volatile(
        "mma.sync.aligned.m16n8k16.row.col.f32.f16.f16.f32 "
        "{%0,%1,%2,%3}, {%4,%5,%6,%7}, {%8,%9}, {%0,%1,%2,%3};"
        : "+f"(d[0]), "+f"(d[1]), "+f"(d[2]), "+f"(d[3])
        : "r"(a[0]), "r"(a[1]), "r"(a[2]), "r"(a[3]), "r"(b[0]), "r"(b[1]));
}

#define LDSM4(r, a) \
    asm volatile("ldmatrix.sync.aligned.m8n8.x4.shared.b16 {%0,%1,%2,%3}, [%4];" \
        : "=r"((r)[0]), "=r"((r)[1]), "=r"((r)[2]), "=r"((r)[3]) : "r"(a))

// =================== K0: O[r][c] = sum_k A[r,k] * B[c,k]  (256x256x256) ======
__global__ __launch_bounds__(256) void gmat_kernel(
    const float* __restrict__ A, const float* __restrict__ B, float* __restrict__ O)
{
    __shared__ float aS[32 * 65];
    __shared__ float bS[32 * 65];
    const int t  = threadIdx.x;
    const int r0 = blockIdx.y * 64;
    const int c0 = blockIdx.x * 64;

    const int lr = t >> 2;
    const int lc = (t & 3) * 8;

    float acc[4][4];
#pragma unroll
    for (int u = 0; u < 4; ++u)
#pragma unroll
        for (int v = 0; v < 4; ++v) acc[u][v] = 0.f;

    for (int k0 = 0; k0 < HH; k0 += 32) {
        __syncthreads();
        float4 a0 = *(const float4*)&A[(size_t)(r0 + lr) * HH + k0 + lc];
        float4 a1 = *(const float4*)&A[(size_t)(r0 + lr) * HH + k0 + lc + 4];
        float4 b0 = *(const float4*)&B[(size_t)(c0 + lr) * HH + k0 + lc];
        float4 b1 = *(const float4*)&B[(size_t)(c0 + lr) * HH + k0 + lc + 4];
        aS[(lc + 0) * 65 + lr] = a0.x; aS[(lc + 1) * 65 + lr] = a0.y;
        aS[(lc + 2) * 65 + lr] = a0.z; aS[(lc + 3) * 65 + lr] = a0.w;
        aS[(lc + 4) * 65 + lr] = a1.x; aS[(lc + 5) * 65 + lr] = a1.y;
        aS[(lc + 6) * 65 + lr] = a1.z; aS[(lc + 7) * 65 + lr] = a1.w;
        bS[(lc + 0) * 65 + lr] = b0.x; bS[(lc + 1) * 65 + lr] = b0.y;
        bS[(lc + 2) * 65 + lr] = b0.z; bS[(lc + 3) * 65 + lr] = b0.w;
        bS[(lc + 4) * 65 + lr] = b1.x; bS[(lc + 5) * 65 + lr] = b1.y;
        bS[(lc + 6) * 65 + lr] = b1.z; bS[(lc + 7) * 65 + lr] = b1.w;
        __syncthreads();

        const int ty = t >> 4, tx = t & 15;
#pragma unroll
        for (int kk = 0; kk < 32; ++kk) {
            float a[4], bb[4];
#pragma unroll
            for (int u = 0; u < 4; ++u) { a[u] = aS[kk * 65 + ty * 4 + u]; bb[u] = bS[kk * 65 + tx * 4 + u]; }
#pragma unroll
            for (int u = 0; u < 4; ++u)
#pragma unroll
                for (int v = 0; v < 4; ++v) acc[u][v] += a[u] * bb[v];
        }
    }

    const int ty = t >> 4, tx = t & 15;
#pragma unroll
    for (int u = 0; u < 4; ++u) {
        float4 r;
        r.x = acc[u][0]; r.y = acc[u][1]; r.z = acc[u][2]; r.w = acc[u][3];
        *(float4*)&O[(size_t)(r0 + ty * 4 + u) * HH + c0 + tx * 4] = r;
    }
}

// ============ split fp32 -> fp16 hi + fp16 lo (elementwise) ==================
__global__ __launch_bounds__(256) void split_kernel(
    const float* __restrict__ in, __half* __restrict__ hi, __half* __restrict__ lo, int n4)
{
    int i = blockIdx.x * 256 + threadIdx.x;
    int stride = gridDim.x * 256;
    for (; i < n4; i += stride) {
        float4 x = ((const float4*)in)[i];
        __half hx = __float2half_rn(x.x), hy = __float2half_rn(x.y);
        __half hz = __float2half_rn(x.z), hw = __float2half_rn(x.w);
        __half lx = __float2half_rn(x.x - __half2float(hx));
        __half ly = __float2half_rn(x.y - __half2float(hy));
        __half lz = __float2half_rn(x.z - __half2float(hz));
        __half lw = __float2half_rn(x.w - __half2float(hw));
        ((__half2*)hi)[i * 2 + 0] = __halves2half2(hx, hy);
        ((__half2*)hi)[i * 2 + 1] = __halves2half2(hz, hw);
        ((__half2*)lo)[i * 2 + 0] = __halves2half2(lx, ly);
        ((__half2*)lo)[i * 2 + 1] = __halves2half2(lz, lw);
    }
}

// =================== v = latent[BS,64] @ Wv[64,64] ===========================
__global__ __launch_bounds__(256) void vproj_kernel(
    const float* __restrict__ X, const float* __restrict__ Wv, float* __restrict__ V)
{
    __shared__ float Ws[64 * 65];
    __shared__ float Xs[32 * 65];
    const int t  = threadIdx.x;
    const int r0 = blockIdx.x * 32;

#pragma unroll
    for (int u = 0; u < 16; ++u) {
        int idx = u * 256 + t; int r = idx >> 6, c = idx & 63;
        Ws[r * 65 + c] = Wv[idx];
    }
#pragma unroll
    for (int u = 0; u < 8; ++u) {
        int idx = u * 256 + t; int r = idx >> 6, c = idx & 63;
        Xs[r * 65 + c] = X[(size_t)(r0 + r) * 64 + c];
    }
    __syncthreads();

    const int row = t >> 3;
    const int c0  = (t & 7) * 8;
    float acc[8];
#pragma unroll
    for (int u = 0; u < 8; ++u) acc[u] = 0.f;
#pragma unroll 8
    for (int z = 0; z < 64; ++z) {
        float a = Xs[row * 65 + z];
#pragma unroll
        for (int u = 0; u < 8; ++u) acc[u] += a * Ws[z * 65 + c0 + u];
    }
#pragma unroll
    for (int u = 0; u < 8; ++u) V[(size_t)(r0 + row) * 64 + c0 + u] = acc[u];
}

// =========== Split-precision HMMA GEMM: C = A @ B^T, K=256 ===================
// CTA tile 128x128, 8 warps (2x4), warp tile 64x32, k-chunk 32, double buffer,
// ldmatrix fragment loads.
// IS_ALIGN=1: write masked/scaled logits + per-CTA-tile column softmax partials
// IS_ALIGN=0: write split fp16 (qhi,qlo)
template<bool IS_ALIGN>
__global__ void __launch_bounds__(256) mma_split_kernel(
    const __half* __restrict__ Ahig, const __half* __restrict__ Alog,
    const __half* __restrict__ Bhig, const __half* __restrict__ Blog,
    const void* __restrict__ mask, float* __restrict__ Cout,
    __half* __restrict__ Qhi, __half* __restrict__ Qlo,
    float* __restrict__ Pmax, float* __restrict__ Psum)
{
    extern __shared__ __half sm[];
    const int t    = threadIdx.x;
    const int lane = t & 31;
    const int wid  = t >> 5;
    const int warpM = wid >> 2;     // 0..1
    const int warpN = wid & 3;      // 0..3
    const int b  = IS_ALIGN ? blockIdx.z : 0;
    const int m0 = blockIdx.y * 128;
    const int n0 = blockIdx.x * 128;

    const size_t arow = IS_ALIGN ? ((size_t)b * SS + m0) : (size_t)m0;
    const size_t brow = IS_ALIGN ? ((size_t)b * SS + n0) : (size_t)n0;
    const __half* Ah = Ahig + arow * HH;
    const __half* Al = Alog + arow * HH;
    const __half* Bh = Bhig + brow * HH;
    const __half* Bl = Blog + brow * HH;

    const uint32_t smbase = smem_u32(sm);

    float acc[4][4][4];
#pragma unroll
    for (int mt = 0; mt < 4; ++mt)
#pragma unroll
        for (int nt = 0; nt < 4; ++nt)
#pragma unroll
            for (int r = 0; r < 4; ++r) acc[mt][nt][r] = 0.f;

    auto issue = [&](int chunk, int p) {
#pragma unroll
        for (int i = 0; i < 8; ++i) {
            const __half* basep = (i < 2) ? Ah : (i < 4) ? Al : (i < 6) ? Bh : Bl;
            const int tile = i >> 1;
            const int flat = i * 256 + t;
            const int w = flat & 511;
            const int r = w >> 2, c16 = w & 3;
            const __half* g = basep + (size_t)r * HH + chunk * 32 + c16 * 8;
            const uint32_t d = smbase +
                (uint32_t)((p * 20480 + tile * 5120 + r * 40 + c16 * 8) * 2);
            asm volatile("cp.async.cg.shared.global [%0], [%1], 16;" :: "r"(d), "l"(g));
        }
        asm volatile("cp.async.commit_group;" ::: "memory");
    };

    issue(0, 0);

    // ldmatrix per-thread address components
    const int aRow = warpM * 64 + (lane & 7) + ((lane >> 3) & 1) * 8;  // + mt*16
    const int aK   = (lane >> 4) * 8;                                   // + k16
    const int bRow = warpN * 32 + (lane & 7) + (lane >> 4) * 8;         // + ntp*16
    const int bK   = ((lane >> 3) & 1) * 8;                             // + k16

    for (int c = 0; c < 8; ++c) {
        asm volatile("cp.async.wait_group 0;" ::: "memory");
        __syncthreads();
        if (c < 7) issue(c + 1, (c + 1) & 1);

        const int p = c & 1;
        const uint32_t abase = smbase + (uint32_t)(p * 20480 * 2);
        const uint32_t bbase = abase + 10240 * 2;

#pragma unroll
        for (int k16 = 0; k16 < 32; k16 += 16) {
            uint32_t ah[4][4], al[4][4], bh[2][4], bl[2][4];
#pragma unroll
            for (int mt = 0; mt < 4; ++mt) {
                const uint32_t adr = abase +
                    (uint32_t)(((aRow + mt * 16) * 40 + k16 + aK) * 2);
                LDSM4(ah[mt], adr);
                LDSM4(al[mt], adr + 10240);
            }
#pragma unroll
            for (int ntp = 0; ntp < 2; ++ntp) {
                const uint32_t adr = bbase +
                    (uint32_t)(((bRow + ntp * 16) * 40 + k16 + bK) * 2);
                LDSM4(bh[ntp], adr);
                LDSM4(bl[ntp], adr + 10240);
            }
#pragma unroll
            for (int mt = 0; mt < 4; ++mt)
#pragma unroll
                for (int nt = 0; nt < 4; ++nt) {
                    const uint32_t bhf[2] = { bh[nt >> 1][(nt & 1) * 2],
                                              bh[nt >> 1][(nt & 1) * 2 + 1] };
                    const uint32_t blf[2] = { bl[nt >> 1][(nt & 1) * 2],
                                              bl[nt >> 1][(nt & 1) * 2 + 1] };
                    hmma16816(acc[mt][nt], ah[mt], bhf);
                    hmma16816(acc[mt][nt], ah[mt], blf);
                    hmma16816(acc[mt][nt], al[mt], bhf);
                }
        }
    }

    // ----------------------------- epilogue ---------------------------------
    if (IS_ALIGN) {
        const bool i32 = mask_is_i32(mask);
        const int*           mi = (const int*)mask;
        const unsigned char* mb = (const unsigned char*)mask;

        // mask+scale into acc, store raw logits
#pragma unroll
        for (int mt = 0; mt < 4; ++mt) {
            const int i = m0 + warpM * 64 + mt * 16 + (lane >> 2);
            const bool k0 = i32 ? (mi[b * SS + i] != 0)     : (mb[b * SS + i] != 0);
            const bool k8 = i32 ? (mi[b * SS + i + 8] != 0) : (mb[b * SS + i + 8] != 0);
            float* row0 = Cout + ((size_t)b * SS + i) * SS;
            float* row8 = row0 + (size_t)8 * SS;
#pragma unroll
            for (int nt = 0; nt < 4; ++nt) {
                const int j = n0 + warpN * 32 + nt * 8 + (lane & 3) * 2;
                acc[mt][nt][0] = k0 ? acc[mt][nt][0] * INV_T : NEGINF;
                acc[mt][nt][1] = k0 ? acc[mt][nt][1] * INV_T : NEGINF;
                acc[mt][nt][2] = k8 ? acc[mt][nt][2] * INV_T : NEGINF;
                acc[mt][nt][3] = k8 ? acc[mt][nt][3] * INV_T : NEGINF;
                float2 v0, v8;
                v0.x = acc[mt][nt][0]; v0.y = acc[mt][nt][1];
                v8.x = acc[mt][nt][2]; v8.y = acc[mt][nt][3];
                *(float2*)&row0[j] = v0;
                *(float2*)&row8[j] = v8;
            }
        }

        // per-CTA column softmax partials (max & sum over the 128 rows)
        float* sMax = (float*)sm;          // [2][128]
        float* sSum = (float*)sm + 256;    // [2][128]
        __syncthreads();                   // MMA smem reads done; safe to reuse

#pragma unroll
        for (int nt = 0; nt < 4; ++nt)
#pragma unroll
            for (int pp = 0; pp < 2; ++pp) {
                float lm = -3.4e38f;
#pragma unroll
                for (int mt = 0; mt < 4; ++mt) {
                    lm = fmaxf(lm, acc[mt][nt][pp]);
                    lm = fmaxf(lm, acc[mt][nt][2 + pp]);
                }
#pragma unroll
                for (int o = 4; o < 32; o <<= 1)
                    lm = fmaxf(lm, __shfl_xor_sync(0xffffffffu, lm, o));
                const int cidx = warpN * 32 + nt * 8 + (lane & 3) * 2 + pp;
                if ((lane >> 2) == 0) sMax[warpM * 128 + cidx] = lm;
            }
        __syncthreads();

#pragma unroll
        for (int nt = 0; nt < 4; ++nt)
#pragma unroll
            for (int pp = 0; pp < 2; ++pp) {
                const int cidx = warpN * 32 + nt * 8 + (lane & 3) * 2 + pp;
                const float cmv = fmaxf(sMax[cidx], sMax[128 + cidx]);
                float ls = 0.f;
#pragma unroll
                for (int mt = 0; mt < 4; ++mt) {
                    ls += fexp(acc[mt][nt][pp] - cmv);
                    ls += fexp(acc[mt][nt][2 + pp] - cmv);
                }
#pragma unroll
                for (int o = 4; o < 32; o <<= 1)
                    ls += __shfl_xor_sync(0xffffffffu, ls, o);
                if ((lane >> 2) == 0) sSum[warpM * 128 + cidx] = ls;
            }
        __syncthreads();

        if (warpM == 0 && (lane >> 2) == 0) {
#pragma unroll
            for (int nt = 0; nt < 4; ++nt)
#pragma unroll
                for (int pp = 0; pp < 2; ++pp) {
                    const int cidx = warpN * 32 + nt * 8 + (lane & 3) * 2 + pp;
                    const float cmv = fmaxf(sMax[cidx], sMax[128 + cidx]);
                    const float tot = sSum[cidx] + sSum[128 + cidx];
                    const size_t o = ((size_t)b * 16 + blockIdx.y) * SS + n0 + cidx;
                    Pmax[o] = cmv;
                    Psum[o] = tot;
                }
        }
    } else {
#pragma unroll
        for (int mt = 0; mt < 4; ++mt) {
            const size_t i = (size_t)m0 + warpM * 64 + mt * 16 + (lane >> 2);
#pragma unroll
            for (int nt = 0; nt < 4; ++nt) {
                const int n = n0 + warpN * 32 + nt * 8 + (lane & 3) * 2;
#pragma unroll
                for (int half = 0; half < 2; ++half) {
                    const size_t row = i + half * 8;
                    float x0 = acc[mt][nt][half * 2 + 0];
                    float x1 = acc[mt][nt][half * 2 + 1];
                    __half h0 = __float2half_rn(x0), h1 = __float2half_rn(x1);
                    __half l0 = __float2half_rn(x0 - __half2float(h0));
                    __half l1 = __float2half_rn(x1 - __half2float(h1));
                    *(__half2*)&Qhi[row * HH + n] = __halves2half2(h0, h1);
                    *(__half2*)&Qlo[row * HH + n] = __halves2half2(l0, l1);
                }
            }
        }
    }
}

// ===== combine per-tile partials into column stats (max, 1/sum) =============
__global__ __launch_bounds__(256) void combine_kernel(
    const float* __restrict__ Pmax, const float* __restrict__ Psum,
    float* __restrict__ cmax, float* __restrict__ rcs)
{
    const int idx = blockIdx.x * 256 + threadIdx.x;    // over B*S
    const int b = idx >> 11, j = idx & 2047;
    float pm[16];
#pragma unroll
    for (int tN = 0; tN < 16; ++tN)
        pm[tN] = Pmax[((size_t)b * 16 + tN) * SS + j];
    float m = pm[0];
#pragma unroll
    for (int tN = 1; tN < 16; ++tN) m = fmaxf(m, pm[tN]);
    float s = 0.f;
#pragma unroll
    for (int tN = 0; tN < 16; ++tN)
        s += Psum[((size_t)b * 16 + tN) * SS + j] * fexp(pm[tN] - m);
    cmax[idx] = m;
    rcs[idx]  = 1.0f / s;
}

// ===== normalize attn in place + output = attn @ v ===========================
__global__ __launch_bounds__(256) void fused_out_kernel(
    float* __restrict__ att, const float* __restrict__ V,
    const float* __restrict__ cmax, const float* __restrict__ rcs,
    float* __restrict__ Out)
{
    __shared__ float attnS[64 * 65];
    __shared__ float vS[64 * 65];
    __shared__ float cmaxS[64];
    __shared__ float rcsS[64];

    const int t  = threadIdx.x;
    const int b  = blockIdx.y;
    const int i0 = blockIdx.x * 64;

    float* attB = att + (size_t)b * SS * SS;
    const float* vB = V + (size_t)b * SS * ZZ;

    const int ty = t >> 4, tx = t & 15;
    float acc[4][4];
#pragma unroll
    for (int u = 0; u < 4; ++u)
#pragma unroll
        for (int v = 0; v < 4; ++v) acc[u][v] = 0.f;

    const int lr = t >> 4;          // 0..15 (row group), float4 col
    const int lc = (t & 15) * 4;    // 0..60

    for (int jt = 0; jt < 32; ++jt) {
        const int j0 = jt * 64;
        __syncthreads();
        if (t < 64)        cmaxS[t] = cmax[b * SS + j0 + t];
        else if (t < 128)  rcsS[t - 64] = rcs[b * SS + j0 + t - 64];
        __syncthreads();

        // normalize 64x64 tile (float4 IO): write attn + stage in smem
#pragma unroll
        for (int u = 0; u < 4; ++u) {
            const int r = u * 16 + lr;
            float4 raw = *(const float4*)&attB[(size_t)(i0 + r) * SS + j0 + lc];
            float4 e;
            e.x = fexp(raw.x - cmaxS[lc + 0]) * rcsS[lc + 0];
            e.y = fexp(raw.y - cmaxS[lc + 1]) * rcsS[lc + 1];
            e.z = fexp(raw.z - cmaxS[lc + 2]) * rcsS[lc + 2];
            e.w = fexp(raw.w - cmaxS[lc + 3]) * rcsS[lc + 3];
            *(float4*)&attB[(size_t)(i0 + r) * SS + j0 + lc] = e;
            attnS[r * 65 + lc + 0] = e.x;
            attnS[r * 65 + lc + 1] = e.y;
            attnS[r * 65 + lc + 2] = e.z;
            attnS[r * 65 + lc + 3] = e.w;
        }
#pragma unroll
        for (int u = 0; u < 4; ++u) {
            const int r = u * 16 + lr;
            float4 vv = *(const float4*)&vB[(size_t)(j0 + r) * ZZ + lc];
            vS[r * 65 + lc + 0] = vv.x;
            vS[r * 65 + lc + 1] = vv.y;
            vS[r * 65 + lc + 2] = vv.z;
            vS[r * 65 + lc + 3] = vv.w;
        }
        __syncthreads();

#pragma unroll 8
        for (int jj = 0; jj < 64; ++jj) {
            float a[4], bv[4];
#pragma unroll
            for (int u = 0; u < 4; ++u) a[u]  = attnS[(ty * 4 + u) * 65 + jj];
#pragma unroll
            for (int v = 0; v < 4; ++v) bv[v] = vS[jj * 65 + tx * 4 + v];
#pragma unroll
            for (int u = 0; u < 4; ++u)
#pragma unroll
                for (int v = 0; v < 4; ++v) acc[u][v] += a[u] * bv[v];
        }
    }

#pragma unroll
    for (int u = 0; u < 4; ++u) {
        size_t row = (size_t)b * SS + i0 + ty * 4 + u;
        float4 r;
        r.x = acc[u][0]; r.y = acc[u][1]; r.z = acc[u][2]; r.w = acc[u][3];
        *(float4*)&Out[row * ZZ + tx * 4] = r;
    }
}

// ============================== launch ======================================
extern "C" void kernel_launch(void* const* d_in, const int* in_sizes, int n_in,
                              void* d_out, int out_size)
{
    const float* enc  = (const float*)d_in[0];
    const float* dec  = (const float*)d_in[1];
    const float* lat  = (const float*)d_in[3];
    const void*  mask = d_in[4];
    const float* Wq   = (const float*)d_in[5];
    const float* Wk   = (const float*)d_in[6];
    const float* Wv   = (const float*)d_in[7];

    float* outp = (float*)d_out;

    const size_t OUTE = (size_t)BB * SS * ZZ;
    const size_t ATTE = (size_t)BB * SS * SS;

    float  *GTp, *vp, *cmaxp, *rcsp, *pmaxp, *psump, *attfb;
    __half *GThi, *GTlo, *dhi, *dlo, *ehi, *elo, *qhi, *qlo;
    cudaGetSymbolAddress((void**)&GTp,   g_GT);
    cudaGetSymbolAddress((void**)&GThi,  g_GThi);
    cudaGetSymbolAddress((void**)&GTlo,  g_GTlo);
    cudaGetSymbolAddress((void**)&dhi,   g_dechi);
    cudaGetSymbolAddress((void**)&dlo,   g_declo);
    cudaGetSymbolAddress((void**)&ehi,   g_ehi);
    cudaGetSymbolAddress((void**)&elo,   g_elo);
    cudaGetSymbolAddress((void**)&qhi,   g_qhi);
    cudaGetSymbolAddress((void**)&qlo,   g_qlo);
    cudaGetSymbolAddress((void**)&vp,    g_v);
    cudaGetSymbolAddress((void**)&pmaxp, g_pmax);
    cudaGetSymbolAddress((void**)&psump, g_psum);
    cudaGetSymbolAddress((void**)&cmaxp, g_cmax);
    cudaGetSymbolAddress((void**)&rcsp,  g_rcs);
    cudaGetSymbolAddress((void**)&attfb, g_att);

    float* attnbuf = ((size_t)out_size >= OUTE + ATTE) ? (outp + OUTE) : attfb;

    const int M = BB * SS;   // 65536

    static int smem_set = 0;
    if (!smem_set) {
        cudaFuncSetAttribute(mma_split_kernel<true>,
                             cudaFuncAttributeMaxDynamicSharedMemorySize, 81920);
        cudaFuncSetAttribute(mma_split_kernel<false>,
                             cudaFuncAttributeMaxDynamicSharedMemorySize, 81920);
        smem_set = 1;
    }

    gmat_kernel<<<dim3(4, 4), 256>>>(Wk, Wq, GTp);
    split_kernel<<<64, 256>>>(GTp, GThi, GTlo, HH * HH / 4);
    split_kernel<<<592, 256>>>(dec, dhi, dlo, M * HH / 4);
    split_kernel<<<592, 256>>>(enc, ehi, elo, M * HH / 4);
    vproj_kernel<<<M / 32, 256>>>(lat, Wv, vp);

    mma_split_kernel<false><<<dim3(HH / 128, M / 128, 1), 256, 81920>>>(
        dhi, dlo, GThi, GTlo, nullptr, nullptr, qhi, qlo, nullptr, nullptr);

    mma_split_kernel<true><<<dim3(SS / 128, SS / 128, BB), 256, 81920>>>(
        qhi, qlo, ehi, elo, mask, attnbuf, nullptr, nullptr, pmaxp, psump);

    combine_kernel<<<(BB * SS) / 256, 256>>>(pmaxp, psump, cmaxp, rcsp);

    fused_out_kernel<<<dim3(SS / 64, BB), 256>>>(attnbuf, vp, cmaxp, rcsp, outp);
}

// round 5
// speedup vs baseline: 2.9194x; 1.0924x over previous
#include <cuda_runtime.h>
#include <cuda_fp16.h>
#include <cstdint>
#include <cstddef>

// Problem sizes (fixed)
#define BB 32
#define SS 2048
#define HH 256
#define ZZ 64

#define INV_T   (0.0625f)   // 1/sqrt(256)
#define NEGINF  (-1e9f)

// ---------------- scratch (device globals; no allocations allowed) ----------
__device__ float  g_GT[HH * HH];
__device__ __half g_GThi[HH * HH];
__device__ __half g_GTlo[HH * HH];
__device__ __half g_dechi[(size_t)BB * SS * HH];
__device__ __half g_declo[(size_t)BB * SS * HH];
__device__ __half g_ehi[(size_t)BB * SS * HH];
__device__ __half g_elo[(size_t)BB * SS * HH];
__device__ __half g_qhi[(size_t)BB * SS * HH];
__device__ __half g_qlo[(size_t)BB * SS * HH];
__device__ float  g_v[(size_t)BB * SS * ZZ];
__device__ __half g_vThi[(size_t)BB * ZZ * SS];   // v^T split, [b][d][s]
__device__ __half g_vTlo[(size_t)BB * ZZ * SS];
__device__ float  g_pmax[(size_t)BB * 16 * SS];   // per-i-tile column max
__device__ float  g_psum[(size_t)BB * 16 * SS];   // per-i-tile column sum
__device__ float  g_cmax[(size_t)BB * SS];
__device__ float  g_rcs[(size_t)BB * SS];         // reciprocal column sum
__device__ float  g_att[(size_t)BB * SS * SS];    // fallback attn buffer

// ---------------- mask dtype detection --------------------------------------
__device__ __forceinline__ bool mask_is_i32(const void* m) {
    const unsigned int* p = (const unsigned int*)m;
    unsigned int o = p[0] | p[1] | p[2] | p[3] | p[4] | p[5] | p[6] | p[7];
    return o <= 1u;
}

__device__ __forceinline__ uint32_t smem_u32(const void* p) {
    uint32_t a;
    asm("{ .reg .u64 t; cvta.to.shared.u64 t, %1; cvt.u32.u64 %0, t; }" : "=r"(a) : "l"(p));
    return a;
}

// FMA-pipe exp (no MUFU): exp(x) = 2^(x*log2e), poly on [-0.5,0.5], rel err ~2e-6
__device__ __forceinline__ float fexp(float x) {
    float y = fmaxf(x * 1.4426950408889634f, -126.0f);
    float r = rintf(y);
    float f = y - r;
    float p =              1.3333558146e-3f;
    p = fmaf(p, f, 9.6181291077e-3f);
    p = fmaf(p, f, 5.5504108664e-2f);
    p = fmaf(p, f, 2.4022650696e-1f);
    p = fmaf(p, f, 6.9314718056e-1f);
    p = fmaf(p, f, 1.0f);
    return __int_as_float(__float_as_int(p) + (((int)r) << 23));
}

__device__ __forceinline__ void hmma16816(float* d, const uint32_t* a, const uint32_t* b) {
    asm volatile(
        "mma.sync.aligned.m16n8k16.row.col.f32.f16.f16.f32 "
        "{%0,%1,%2,%3}, {%4,%5,%6,%7}, {%8,%9}, {%0,%1,%2,%3};"
        : "+f"(d[0]), "+f"(d[1]), "+f"(d[2]), "+f"(d[3])
        : "r"(a[0]), "r"(a[1]), "r"(a[2]), "r"(a[3]), "r"(b[0]), "r"(b[1]));
}

#define LDSM4(r, a) \
    asm volatile("ldmatrix.sync.aligned.m8n8.x4.shared.b16 {%0,%1,%2,%3}, [%4];" \
        : "=r"((r)[0]), "=r"((r)[1]), "=r"((r)[2]), "=r"((r)[3]) : "r"(a))

// =================== K0: O[r][c] = sum_k A[r,k] * B[c,k]  (256x256x256) ======
__global__ __launch_bounds__(256) void gmat_kernel(
    const float* __restrict__ A, const float* __restrict__ B, float* __restrict__ O)
{
    __shared__ float aS[32 * 65];
    __shared__ float bS[32 * 65];
    const int t  = threadIdx.x;
    const int r0 = blockIdx.y * 64;
    const int c0 = blockIdx.x * 64;

    const int lr = t >> 2;
    const int lc = (t & 3) * 8;

    float acc[4][4];
#pragma unroll
    for (int u = 0; u < 4; ++u)
#pragma unroll
        for (int v = 0; v < 4; ++v) acc[u][v] = 0.f;

    for (int k0 = 0; k0 < HH; k0 += 32) {
        __syncthreads();
        float4 a0 = *(const float4*)&A[(size_t)(r0 + lr) * HH + k0 + lc];
        float4 a1 = *(const float4*)&A[(size_t)(r0 + lr) * HH + k0 + lc + 4];
        float4 b0 = *(const float4*)&B[(size_t)(c0 + lr) * HH + k0 + lc];
        float4 b1 = *(const float4*)&B[(size_t)(c0 + lr) * HH + k0 + lc + 4];
        aS[(lc + 0) * 65 + lr] = a0.x; aS[(lc + 1) * 65 + lr] = a0.y;
        aS[(lc + 2) * 65 + lr] = a0.z; aS[(lc + 3) * 65 + lr] = a0.w;
        aS[(lc + 4) * 65 + lr] = a1.x; aS[(lc + 5) * 65 + lr] = a1.y;
        aS[(lc + 6) * 65 + lr] = a1.z; aS[(lc + 7) * 65 + lr] = a1.w;
        bS[(lc + 0) * 65 + lr] = b0.x; bS[(lc + 1) * 65 + lr] = b0.y;
        bS[(lc + 2) * 65 + lr] = b0.z; bS[(lc + 3) * 65 + lr] = b0.w;
        bS[(lc + 4) * 65 + lr] = b1.x; bS[(lc + 5) * 65 + lr] = b1.y;
        bS[(lc + 6) * 65 + lr] = b1.z; bS[(lc + 7) * 65 + lr] = b1.w;
        __syncthreads();

        const int ty = t >> 4, tx = t & 15;
#pragma unroll
        for (int kk = 0; kk < 32; ++kk) {
            float a[4], bb[4];
#pragma unroll
            for (int u = 0; u < 4; ++u) { a[u] = aS[kk * 65 + ty * 4 + u]; bb[u] = bS[kk * 65 + tx * 4 + u]; }
#pragma unroll
            for (int u = 0; u < 4; ++u)
#pragma unroll
                for (int v = 0; v < 4; ++v) acc[u][v] += a[u] * bb[v];
        }
    }

    const int ty = t >> 4, tx = t & 15;
#pragma unroll
    for (int u = 0; u < 4; ++u) {
        float4 r;
        r.x = acc[u][0]; r.y = acc[u][1]; r.z = acc[u][2]; r.w = acc[u][3];
        *(float4*)&O[(size_t)(r0 + ty * 4 + u) * HH + c0 + tx * 4] = r;
    }
}

// ============ split fp32 -> fp16 hi + fp16 lo (elementwise) ==================
__global__ __launch_bounds__(256) void split_kernel(
    const float* __restrict__ in, __half* __restrict__ hi, __half* __restrict__ lo, int n4)
{
    int i = blockIdx.x * 256 + threadIdx.x;
    int stride = gridDim.x * 256;
    for (; i < n4; i += stride) {
        float4 x = ((const float4*)in)[i];
        __half hx = __float2half_rn(x.x), hy = __float2half_rn(x.y);
        __half hz = __float2half_rn(x.z), hw = __float2half_rn(x.w);
        __half lx = __float2half_rn(x.x - __half2float(hx));
        __half ly = __float2half_rn(x.y - __half2float(hy));
        __half lz = __float2half_rn(x.z - __half2float(hz));
        __half lw = __float2half_rn(x.w - __half2float(hw));
        ((__half2*)hi)[i * 2 + 0] = __halves2half2(hx, hy);
        ((__half2*)hi)[i * 2 + 1] = __halves2half2(hz, hw);
        ((__half2*)lo)[i * 2 + 0] = __halves2half2(lx, ly);
        ((__half2*)lo)[i * 2 + 1] = __halves2half2(lz, lw);
    }
}

// =================== v = latent[BS,64] @ Wv[64,64] ===========================
__global__ __launch_bounds__(256) void vproj_kernel(
    const float* __restrict__ X, const float* __restrict__ Wv, float* __restrict__ V)
{
    __shared__ float Ws[64 * 65];
    __shared__ float Xs[32 * 65];
    const int t  = threadIdx.x;
    const int r0 = blockIdx.x * 32;

#pragma unroll
    for (int u = 0; u < 16; ++u) {
        int idx = u * 256 + t; int r = idx >> 6, c = idx & 63;
        Ws[r * 65 + c] = Wv[idx];
    }
#pragma unroll
    for (int u = 0; u < 8; ++u) {
        int idx = u * 256 + t; int r = idx >> 6, c = idx & 63;
        Xs[r * 65 + c] = X[(size_t)(r0 + r) * 64 + c];
    }
    __syncthreads();

    const int row = t >> 3;
    const int c0  = (t & 7) * 8;
    float acc[8];
#pragma unroll
    for (int u = 0; u < 8; ++u) acc[u] = 0.f;
#pragma unroll 8
    for (int z = 0; z < 64; ++z) {
        float a = Xs[row * 65 + z];
#pragma unroll
        for (int u = 0; u < 8; ++u) acc[u] += a * Ws[z * 65 + c0 + u];
    }
#pragma unroll
    for (int u = 0; u < 8; ++u) V[(size_t)(r0 + row) * 64 + c0 + u] = acc[u];
}

// ============ transpose + split v: [b][s][d] fp32 -> [b][d][s] fp16 hi/lo ====
__global__ __launch_bounds__(256) void vtrans_kernel(
    const float* __restrict__ V, __half* __restrict__ vThi, __half* __restrict__ vTlo)
{
    __shared__ float s[64][65];
    const int t  = threadIdx.x;
    const int b  = blockIdx.y;
    const int s0 = blockIdx.x * 64;

#pragma unroll
    for (int i = 0; i < 4; ++i) {
        int flat = i * 256 + t;
        int r = flat >> 4, c = (flat & 15) * 4;
        float4 x = *(const float4*)&V[((size_t)b * SS + s0 + r) * ZZ + c];
        s[r][c] = x.x; s[r][c + 1] = x.y; s[r][c + 2] = x.z; s[r][c + 3] = x.w;
    }
    __syncthreads();

#pragma unroll
    for (int i = 0; i < 4; ++i) {
        int flat = i * 256 + t;
        int d = flat >> 4, sc = (flat & 15) * 4;
        __half h[4], l[4];
#pragma unroll
        for (int k = 0; k < 4; ++k) {
            float x = s[sc + k][d];
            h[k] = __float2half_rn(x);
            l[k] = __float2half_rn(x - __half2float(h[k]));
        }
        size_t o = ((size_t)b * ZZ + d) * SS + s0 + sc;
        *(__half2*)&vThi[o]     = __halves2half2(h[0], h[1]);
        *(__half2*)&vThi[o + 2] = __halves2half2(h[2], h[3]);
        *(__half2*)&vTlo[o]     = __halves2half2(l[0], l[1]);
        *(__half2*)&vTlo[o + 2] = __halves2half2(l[2], l[3]);
    }
}

// =========== Split-precision HMMA GEMM: C = A @ B^T, K=256 ===================
// CTA tile 128x128, 8 warps (2x4), warp tile 64x32, k-chunk 32, double buffer.
// IS_ALIGN=1: write masked/scaled logits + per-CTA-tile column softmax partials
// IS_ALIGN=0: write split fp16 (qhi,qlo)
template<bool IS_ALIGN>
__global__ void __launch_bounds__(256) mma_split_kernel(
    const __half* __restrict__ Ahig, const __half* __restrict__ Alog,
    const __half* __restrict__ Bhig, const __half* __restrict__ Blog,
    const void* __restrict__ mask, float* __restrict__ Cout,
    __half* __restrict__ Qhi, __half* __restrict__ Qlo,
    float* __restrict__ Pmax, float* __restrict__ Psum)
{
    extern __shared__ __half sm[];
    const int t    = threadIdx.x;
    const int lane = t & 31;
    const int wid  = t >> 5;
    const int warpM = wid >> 2;
    const int warpN = wid & 3;
    const int b  = IS_ALIGN ? blockIdx.z : 0;
    const int m0 = blockIdx.y * 128;
    const int n0 = blockIdx.x * 128;

    const size_t arow = IS_ALIGN ? ((size_t)b * SS + m0) : (size_t)m0;
    const size_t brow = IS_ALIGN ? ((size_t)b * SS + n0) : (size_t)n0;
    const __half* Ah = Ahig + arow * HH;
    const __half* Al = Alog + arow * HH;
    const __half* Bh = Bhig + brow * HH;
    const __half* Bl = Blog + brow * HH;

    const uint32_t smbase = smem_u32(sm);

    float acc[4][4][4];
#pragma unroll
    for (int mt = 0; mt < 4; ++mt)
#pragma unroll
        for (int nt = 0; nt < 4; ++nt)
#pragma unroll
            for (int r = 0; r < 4; ++r) acc[mt][nt][r] = 0.f;

    auto issue = [&](int chunk, int p) {
#pragma unroll
        for (int i = 0; i < 8; ++i) {
            const __half* basep = (i < 2) ? Ah : (i < 4) ? Al : (i < 6) ? Bh : Bl;
            const int tile = i >> 1;
            const int flat = i * 256 + t;
            const int w = flat & 511;
            const int r = w >> 2, c16 = w & 3;
            const __half* g = basep + (size_t)r * HH + chunk * 32 + c16 * 8;
            const uint32_t d = smbase +
                (uint32_t)((p * 20480 + tile * 5120 + r * 40 + c16 * 8) * 2);
            asm volatile("cp.async.cg.shared.global [%0], [%1], 16;" :: "r"(d), "l"(g));
        }
        asm volatile("cp.async.commit_group;" ::: "memory");
    };

    issue(0, 0);

    const int aRow = warpM * 64 + (lane & 7) + ((lane >> 3) & 1) * 8;
    const int aK   = (lane >> 4) * 8;
    const int bRow = warpN * 32 + (lane & 7) + (lane >> 4) * 8;
    const int bK   = ((lane >> 3) & 1) * 8;

    for (int c = 0; c < 8; ++c) {
        asm volatile("cp.async.wait_group 0;" ::: "memory");
        __syncthreads();
        if (c < 7) issue(c + 1, (c + 1) & 1);

        const int p = c & 1;
        const uint32_t abase = smbase + (uint32_t)(p * 20480 * 2);
        const uint32_t bbase = abase + 10240 * 2;

#pragma unroll
        for (int k16 = 0; k16 < 32; k16 += 16) {
            uint32_t ah[4][4], al[4][4], bh[2][4], bl[2][4];
#pragma unroll
            for (int mt = 0; mt < 4; ++mt) {
                const uint32_t adr = abase +
                    (uint32_t)(((aRow + mt * 16) * 40 + k16 + aK) * 2);
                LDSM4(ah[mt], adr);
                LDSM4(al[mt], adr + 10240);
            }
#pragma unroll
            for (int ntp = 0; ntp < 2; ++ntp) {
                const uint32_t adr = bbase +
                    (uint32_t)(((bRow + ntp * 16) * 40 + k16 + bK) * 2);
                LDSM4(bh[ntp], adr);
                LDSM4(bl[ntp], adr + 10240);
            }
#pragma unroll
            for (int mt = 0; mt < 4; ++mt)
#pragma unroll
                for (int nt = 0; nt < 4; ++nt) {
                    const uint32_t bhf[2] = { bh[nt >> 1][(nt & 1) * 2],
                                              bh[nt >> 1][(nt & 1) * 2 + 1] };
                    const uint32_t blf[2] = { bl[nt >> 1][(nt & 1) * 2],
                                              bl[nt >> 1][(nt & 1) * 2 + 1] };
                    hmma16816(acc[mt][nt], ah[mt], bhf);
                    hmma16816(acc[mt][nt], ah[mt], blf);
                    hmma16816(acc[mt][nt], al[mt], bhf);
                }
        }
    }

    // ----------------------------- epilogue ---------------------------------
    if (IS_ALIGN) {
        const bool i32 = mask_is_i32(mask);
        const int*           mi = (const int*)mask;
        const unsigned char* mb = (const unsigned char*)mask;

#pragma unroll
        for (int mt = 0; mt < 4; ++mt) {
            const int i = m0 + warpM * 64 + mt * 16 + (lane >> 2);
            const bool k0 = i32 ? (mi[b * SS + i] != 0)     : (mb[b * SS + i] != 0);
            const bool k8 = i32 ? (mi[b * SS + i + 8] != 0) : (mb[b * SS + i + 8] != 0);
            float* row0 = Cout + ((size_t)b * SS + i) * SS;
            float* row8 = row0 + (size_t)8 * SS;
#pragma unroll
            for (int nt = 0; nt < 4; ++nt) {
                const int j = n0 + warpN * 32 + nt * 8 + (lane & 3) * 2;
                acc[mt][nt][0] = k0 ? acc[mt][nt][0] * INV_T : NEGINF;
                acc[mt][nt][1] = k0 ? acc[mt][nt][1] * INV_T : NEGINF;
                acc[mt][nt][2] = k8 ? acc[mt][nt][2] * INV_T : NEGINF;
                acc[mt][nt][3] = k8 ? acc[mt][nt][3] * INV_T : NEGINF;
                float2 v0, v8;
                v0.x = acc[mt][nt][0]; v0.y = acc[mt][nt][1];
                v8.x = acc[mt][nt][2]; v8.y = acc[mt][nt][3];
                *(float2*)&row0[j] = v0;
                *(float2*)&row8[j] = v8;
            }
        }

        float* sMax = (float*)sm;
        float* sSum = (float*)sm + 256;
        __syncthreads();

#pragma unroll
        for (int nt = 0; nt < 4; ++nt)
#pragma unroll
            for (int pp = 0; pp < 2; ++pp) {
                float lm = -3.4e38f;
#pragma unroll
                for (int mt = 0; mt < 4; ++mt) {
                    lm = fmaxf(lm, acc[mt][nt][pp]);
                    lm = fmaxf(lm, acc[mt][nt][2 + pp]);
                }
#pragma unroll
                for (int o = 4; o < 32; o <<= 1)
                    lm = fmaxf(lm, __shfl_xor_sync(0xffffffffu, lm, o));
                const int cidx = warpN * 32 + nt * 8 + (lane & 3) * 2 + pp;
                if ((lane >> 2) == 0) sMax[warpM * 128 + cidx] = lm;
            }
        __syncthreads();

#pragma unroll
        for (int nt = 0; nt < 4; ++nt)
#pragma unroll
            for (int pp = 0; pp < 2; ++pp) {
                const int cidx = warpN * 32 + nt * 8 + (lane & 3) * 2 + pp;
                const float cmv = fmaxf(sMax[cidx], sMax[128 + cidx]);
                float ls = 0.f;
#pragma unroll
                for (int mt = 0; mt < 4; ++mt) {
                    ls += fexp(acc[mt][nt][pp] - cmv);
                    ls += fexp(acc[mt][nt][2 + pp] - cmv);
                }
#pragma unroll
                for (int o = 4; o < 32; o <<= 1)
                    ls += __shfl_xor_sync(0xffffffffu, ls, o);
                if ((lane >> 2) == 0) sSum[warpM * 128 + cidx] = ls;
            }
        __syncthreads();

        if (warpM == 0 && (lane >> 2) == 0) {
#pragma unroll
            for (int nt = 0; nt < 4; ++nt)
#pragma unroll
                for (int pp = 0; pp < 2; ++pp) {
                    const int cidx = warpN * 32 + nt * 8 + (lane & 3) * 2 + pp;
                    const float cmv = fmaxf(sMax[cidx], sMax[128 + cidx]);
                    const float tot = sSum[cidx] + sSum[128 + cidx];
                    const size_t o = ((size_t)b * 16 + blockIdx.y) * SS + n0 + cidx;
                    Pmax[o] = cmv;
                    Psum[o] = tot;
                }
        }
    } else {
#pragma unroll
        for (int mt = 0; mt < 4; ++mt) {
            const size_t i = (size_t)m0 + warpM * 64 + mt * 16 + (lane >> 2);
#pragma unroll
            for (int nt = 0; nt < 4; ++nt) {
                const int n = n0 + warpN * 32 + nt * 8 + (lane & 3) * 2;
#pragma unroll
                for (int half = 0; half < 2; ++half) {
                    const size_t row = i + half * 8;
                    float x0 = acc[mt][nt][half * 2 + 0];
                    float x1 = acc[mt][nt][half * 2 + 1];
                    __half h0 = __float2half_rn(x0), h1 = __float2half_rn(x1);
                    __half l0 = __float2half_rn(x0 - __half2float(h0));
                    __half l1 = __float2half_rn(x1 - __half2float(h1));
                    *(__half2*)&Qhi[row * HH + n] = __halves2half2(h0, h1);
                    *(__half2*)&Qlo[row * HH + n] = __halves2half2(l0, l1);
                }
            }
        }
    }
}

// ===== combine per-tile partials into column stats (max, 1/sum) =============
__global__ __launch_bounds__(256) void combine_kernel(
    const float* __restrict__ Pmax, const float* __restrict__ Psum,
    float* __restrict__ cmax, float* __restrict__ rcs)
{
    const int idx = blockIdx.x * 256 + threadIdx.x;
    const int b = idx >> 11, j = idx & 2047;
    float pm[16];
#pragma unroll
    for (int tN = 0; tN < 16; ++tN)
        pm[tN] = Pmax[((size_t)b * 16 + tN) * SS + j];
    float m = pm[0];
#pragma unroll
    for (int tN = 1; tN < 16; ++tN) m = fmaxf(m, pm[tN]);
    float s = 0.f;
#pragma unroll
    for (int tN = 0; tN < 16; ++tN)
        s += Psum[((size_t)b * 16 + tN) * SS + j] * fexp(pm[tN] - m);
    cmax[idx] = m;
    rcs[idx]  = 1.0f / s;
}

// ===== normalize attn in place + output = attn @ v  (HMMA split) ============
// CTA: 128 i-rows x full Z=64, loops over 32 j-chunks of 64.
__global__ void __launch_bounds__(256) fused_out_mma_kernel(
    float* __restrict__ att, const __half* __restrict__ vThi,
    const __half* __restrict__ vTlo, const float* __restrict__ cmax,
    const float* __restrict__ rcs, float* __restrict__ Out)
{
    extern __shared__ __half sm[];
    // halves offsets: attnHi [128][72] @0, attnLo @9216, vHi [64][72] @18432, vLo @23040
    float* cmaxS = (float*)(sm + 27648);
    float* rcsS  = cmaxS + 64;

    const int t    = threadIdx.x;
    const int lane = t & 31;
    const int wid  = t >> 5;
    const int warpM = wid >> 2;     // 0..1
    const int warpN = wid & 3;      // 0..3
    const int b  = blockIdx.y;
    const int i0 = blockIdx.x * 128;

    float* attB = att + (size_t)b * SS * SS;
    const __half* vhB = vThi + (size_t)b * ZZ * SS;
    const __half* vlB = vTlo + (size_t)b * ZZ * SS;

    const uint32_t smb = smem_u32(sm);

    float acc[4][2][4];
#pragma unroll
    for (int mt = 0; mt < 4; ++mt)
#pragma unroll
        for (int nt = 0; nt < 2; ++nt)
#pragma unroll
            for (int r = 0; r < 4; ++r) acc[mt][nt][r] = 0.f;

    const int aRow = warpM * 64 + (lane & 7) + ((lane >> 3) & 1) * 8;
    const int aK   = (lane >> 4) * 8;
    const int bRow = warpN * 16 + (lane & 7) + (lane >> 4) * 8;
    const int bK   = ((lane >> 3) & 1) * 8;

    const int lr = t >> 4;          // 0..15
    const int lc = (t & 15) * 4;    // 0..60

    for (int jt = 0; jt < 32; ++jt) {
        const int j0 = jt * 64;
        __syncthreads();   // previous chunk's MMA reads done

        if (t < 64)        cmaxS[t] = cmax[b * SS + j0 + t];
        else if (t < 128)  rcsS[t - 64] = rcs[b * SS + j0 + t - 64];

        // cp.async v^T tiles (64 d-rows x 64 j-cols, hi+lo)
#pragma unroll
        for (int i = 0; i < 2; ++i) {
            const int flat = i * 256 + t;
            const int r = flat >> 3, c = (flat & 7) * 8;
            const __half* gh = vhB + (size_t)r * SS + j0 + c;
            const __half* gl = vlB + (size_t)r * SS + j0 + c;
            const uint32_t dh = smb + (uint32_t)((18432 + r * 72 + c) * 2);
            const uint32_t dl = smb + (uint32_t)((23040 + r * 72 + c) * 2);
            asm volatile("cp.async.cg.shared.global [%0], [%1], 16;" :: "r"(dh), "l"(gh));
            asm volatile("cp.async.cg.shared.global [%0], [%1], 16;" :: "r"(dl), "l"(gl));
        }
        asm volatile("cp.async.commit_group;" ::: "memory");
        __syncthreads();   // cmaxS/rcsS visible

        // normalize 128x64 tile: float4 read, exp, write back, split to smem
#pragma unroll
        for (int u = 0; u < 8; ++u) {
            const int r = u * 16 + lr;
            float4 raw = *(const float4*)&attB[(size_t)(i0 + r) * SS + j0 + lc];
            float4 e;
            e.x = fexp(raw.x - cmaxS[lc + 0]) * rcsS[lc + 0];
            e.y = fexp(raw.y - cmaxS[lc + 1]) * rcsS[lc + 1];
            e.z = fexp(raw.z - cmaxS[lc + 2]) * rcsS[lc + 2];
            e.w = fexp(raw.w - cmaxS[lc + 3]) * rcsS[lc + 3];
            *(float4*)&attB[(size_t)(i0 + r) * SS + j0 + lc] = e;
            __half hx = __float2half_rn(e.x), hy = __float2half_rn(e.y);
            __half hz = __float2half_rn(e.z), hw = __float2half_rn(e.w);
            __half lx = __float2half_rn(e.x - __half2float(hx));
            __half ly = __float2half_rn(e.y - __half2float(hy));
            __half lz = __float2half_rn(e.z - __half2float(hz));
            __half lw = __float2half_rn(e.w - __half2float(hw));
            __half2* ph = (__half2*)&sm[r * 72 + lc];
            ph[0] = __halves2half2(hx, hy);
            ph[1] = __halves2half2(hz, hw);
            __half2* pl = (__half2*)&sm[9216 + r * 72 + lc];
            pl[0] = __halves2half2(lx, ly);
            pl[1] = __halves2half2(lz, lw);
        }
        asm volatile("cp.async.wait_group 0;" ::: "memory");
        __syncthreads();

        // MMA: M128 x N64 x K64 (attn hi/lo x v hi/lo, 3 terms)
#pragma unroll
        for (int k16 = 0; k16 < 64; k16 += 16) {
            uint32_t ah[4][4], al[4][4], bh[4], bl[4];
#pragma unroll
            for (int mt = 0; mt < 4; ++mt) {
                const uint32_t adr = smb +
                    (uint32_t)(((aRow + mt * 16) * 72 + k16 + aK) * 2);
                LDSM4(ah[mt], adr);
                LDSM4(al[mt], adr + 9216 * 2);
            }
            const uint32_t badr = smb +
                (uint32_t)((18432 + bRow * 72 + k16 + bK) * 2);
            LDSM4(bh, badr);
            LDSM4(bl, badr + 4608 * 2);
#pragma unroll
            for (int mt = 0; mt < 4; ++mt)
#pragma unroll
                for (int nt = 0; nt < 2; ++nt) {
                    const uint32_t bhf[2] = { bh[nt * 2], bh[nt * 2 + 1] };
                    const uint32_t blf[2] = { bl[nt * 2], bl[nt * 2 + 1] };
                    hmma16816(acc[mt][nt], ah[mt], bhf);
                    hmma16816(acc[mt][nt], ah[mt], blf);
                    hmma16816(acc[mt][nt], al[mt], bhf);
                }
        }
    }

    // epilogue: Out[b][i][d]
#pragma unroll
    for (int mt = 0; mt < 4; ++mt) {
        const int i = i0 + warpM * 64 + mt * 16 + (lane >> 2);
#pragma unroll
        for (int nt = 0; nt < 2; ++nt) {
            const int d = warpN * 16 + nt * 8 + (lane & 3) * 2;
            float2 v0, v8;
            v0.x = acc[mt][nt][0]; v0.y = acc[mt][nt][1];
            v8.x = acc[mt][nt][2]; v8.y = acc[mt][nt][3];
            *(float2*)&Out[((size_t)b * SS + i) * ZZ + d]     = v0;
            *(float2*)&Out[((size_t)b * SS + i + 8) * ZZ + d] = v8;
        }
    }
}

// ============================== launch ======================================
extern "C" void kernel_launch(void* const* d_in, const int* in_sizes, int n_in,
                              void* d_out, int out_size)
{
    const float* enc  = (const float*)d_in[0];
    const float* dec  = (const float*)d_in[1];
    const float* lat  = (const float*)d_in[3];
    const void*  mask = d_in[4];
    const float* Wq   = (const float*)d_in[5];
    const float* Wk   = (const float*)d_in[6];
    const float* Wv   = (const float*)d_in[7];

    float* outp = (float*)d_out;

    const size_t OUTE = (size_t)BB * SS * ZZ;
    const size_t ATTE = (size_t)BB * SS * SS;

    float  *GTp, *vp, *cmaxp, *rcsp, *pmaxp, *psump, *attfb;
    __half *GThi, *GTlo, *dhi, *dlo, *ehi, *elo, *qhi, *qlo, *vthi, *vtlo;
    cudaGetSymbolAddress((void**)&GTp,   g_GT);
    cudaGetSymbolAddress((void**)&GThi,  g_GThi);
    cudaGetSymbolAddress((void**)&GTlo,  g_GTlo);
    cudaGetSymbolAddress((void**)&dhi,   g_dechi);
    cudaGetSymbolAddress((void**)&dlo,   g_declo);
    cudaGetSymbolAddress((void**)&ehi,   g_ehi);
    cudaGetSymbolAddress((void**)&elo,   g_elo);
    cudaGetSymbolAddress((void**)&qhi,   g_qhi);
    cudaGetSymbolAddress((void**)&qlo,   g_qlo);
    cudaGetSymbolAddress((void**)&vp,    g_v);
    cudaGetSymbolAddress((void**)&vthi,  g_vThi);
    cudaGetSymbolAddress((void**)&vtlo,  g_vTlo);
    cudaGetSymbolAddress((void**)&pmaxp, g_pmax);
    cudaGetSymbolAddress((void**)&psump, g_psum);
    cudaGetSymbolAddress((void**)&cmaxp, g_cmax);
    cudaGetSymbolAddress((void**)&rcsp,  g_rcs);
    cudaGetSymbolAddress((void**)&attfb, g_att);

    float* attnbuf = ((size_t)out_size >= OUTE + ATTE) ? (outp + OUTE) : attfb;

    const int M = BB * SS;   // 65536

    static int smem_set = 0;
    if (!smem_set) {
        cudaFuncSetAttribute(mma_split_kernel<true>,
                             cudaFuncAttributeMaxDynamicSharedMemorySize, 81920);
        cudaFuncSetAttribute(mma_split_kernel<false>,
                             cudaFuncAttributeMaxDynamicSharedMemorySize, 81920);
        cudaFuncSetAttribute(fused_out_mma_kernel,
                             cudaFuncAttributeMaxDynamicSharedMemorySize, 56320);
        smem_set = 1;
    }

    gmat_kernel<<<dim3(4, 4), 256>>>(Wk, Wq, GTp);
    split_kernel<<<64, 256>>>(GTp, GThi, GTlo, HH * HH / 4);
    split_kernel<<<592, 256>>>(dec, dhi, dlo, M * HH / 4);
    split_kernel<<<592, 256>>>(enc, ehi, elo, M * HH / 4);
    vproj_kernel<<<M / 32, 256>>>(lat, Wv, vp);
    vtrans_kernel<<<dim3(SS / 64, BB), 256>>>(vp, vthi, vtlo);

    mma_split_kernel<false><<<dim3(HH / 128, M / 128, 1), 256, 81920>>>(
        dhi, dlo, GThi, GTlo, nullptr, nullptr, qhi, qlo, nullptr, nullptr);

    mma_split_kernel<true><<<dim3(SS / 128, SS / 128, BB), 256, 81920>>>(
        qhi, qlo, ehi, elo, mask, attnbuf, nullptr, nullptr, pmaxp, psump);

    combine_kernel<<<(BB * SS) / 256, 256>>>(pmaxp, psump, cmaxp, rcsp);

    fused_out_mma_kernel<<<dim3(SS / 128, BB), 256, 56320>>>(
        attnbuf, vthi, vtlo, cmaxp, rcsp, outp);
}

// round 6
// speedup vs baseline: 3.5539x; 1.2174x over previous
#include <cuda_runtime.h>
#include <cuda_fp16.h>
#include <cstdint>
#include <cstddef>

// Problem sizes (fixed)
#define BB 32
#define SS 2048
#define HH 256
#define ZZ 64

#define INV_T   (0.0625f)   // 1/sqrt(256)
#define NEGINF  (-1e9f)

// ---------------- scratch (device globals; no allocations allowed) ----------
__device__ float  g_GT[HH * HH];
__device__ __half g_GThi[HH * HH];
__device__ __half g_GTlo[HH * HH];
__device__ __half g_dechi[(size_t)BB * SS * HH];
__device__ __half g_declo[(size_t)BB * SS * HH];
__device__ __half g_ehi[(size_t)BB * SS * HH];
__device__ __half g_elo[(size_t)BB * SS * HH];
__device__ __half g_qhi[(size_t)BB * SS * HH];
__device__ __half g_qlo[(size_t)BB * SS * HH];
__device__ float  g_v[(size_t)BB * SS * ZZ];
__device__ __half g_vThi[(size_t)BB * ZZ * SS];   // v^T split, [b][d][s]
__device__ __half g_vTlo[(size_t)BB * ZZ * SS];
__device__ __half g_patt[(size_t)BB * SS * SS];   // p = exp(x - tilemax), fp16
__device__ float  g_pmax[(size_t)BB * 16 * SS];   // per-i-tile column max
__device__ float  g_psum[(size_t)BB * 16 * SS];   // per-i-tile column sum
__device__ float  g_cmax[(size_t)BB * SS];
__device__ float  g_rcs[(size_t)BB * SS];         // reciprocal column sum
__device__ float  g_att[(size_t)BB * SS * SS];    // fallback attn buffer

// ---------------- mask dtype detection --------------------------------------
__device__ __forceinline__ bool mask_is_i32(const void* m) {
    const unsigned int* p = (const unsigned int*)m;
    unsigned int o = p[0] | p[1] | p[2] | p[3] | p[4] | p[5] | p[6] | p[7];
    return o <= 1u;
}

__device__ __forceinline__ uint32_t smem_u32(const void* p) {
    uint32_t a;
    asm("{ .reg .u64 t; cvta.to.shared.u64 t, %1; cvt.u32.u64 %0, t; }" : "=r"(a) : "l"(p));
    return a;
}

// FMA-pipe exp (no MUFU): exp(x) = 2^(x*log2e), poly on [-0.5,0.5], rel err ~2e-6
__device__ __forceinline__ float fexp(float x) {
    float y = fmaxf(x * 1.4426950408889634f, -126.0f);
    float r = rintf(y);
    float f = y - r;
    float p =              1.3333558146e-3f;
    p = fmaf(p, f, 9.6181291077e-3f);
    p = fmaf(p, f, 5.5504108664e-2f);
    p = fmaf(p, f, 2.4022650696e-1f);
    p = fmaf(p, f, 6.9314718056e-1f);
    p = fmaf(p, f, 1.0f);
    return __int_as_float(__float_as_int(p) + (((int)r) << 23));
}

__device__ __forceinline__ void hmma16816(float* d, const uint32_t* a, const uint32_t* b) {
    asm volatile(
        "mma.sync.aligned.m16n8k16.row.col.f32.f16.f16.f32 "
        "{%0,%1,%2,%3}, {%4,%5,%6,%7}, {%8,%9}, {%0,%1,%2,%3};"
        : "+f"(d[0]), "+f"(d[1]), "+f"(d[2]), "+f"(d[3])
        : "r"(a[0]), "r"(a[1]), "r"(a[2]), "r"(a[3]), "r"(b[0]), "r"(b[1]));
}

#define LDSM4(r, a) \
    asm volatile("ldmatrix.sync.aligned.m8n8.x4.shared.b16 {%0,%1,%2,%3}, [%4];" \
        : "=r"((r)[0]), "=r"((r)[1]), "=r"((r)[2]), "=r"((r)[3]) : "r"(a))

// =================== K0: O[r][c] = sum_k A[r,k] * B[c,k]  (256x256x256) ======
__global__ __launch_bounds__(256) void gmat_kernel(
    const float* __restrict__ A, const float* __restrict__ B, float* __restrict__ O)
{
    __shared__ float aS[32 * 65];
    __shared__ float bS[32 * 65];
    const int t  = threadIdx.x;
    const int r0 = blockIdx.y * 64;
    const int c0 = blockIdx.x * 64;

    const int lr = t >> 2;
    const int lc = (t & 3) * 8;

    float acc[4][4];
#pragma unroll
    for (int u = 0; u < 4; ++u)
#pragma unroll
        for (int v = 0; v < 4; ++v) acc[u][v] = 0.f;

    for (int k0 = 0; k0 < HH; k0 += 32) {
        __syncthreads();
        float4 a0 = *(const float4*)&A[(size_t)(r0 + lr) * HH + k0 + lc];
        float4 a1 = *(const float4*)&A[(size_t)(r0 + lr) * HH + k0 + lc + 4];
        float4 b0 = *(const float4*)&B[(size_t)(c0 + lr) * HH + k0 + lc];
        float4 b1 = *(const float4*)&B[(size_t)(c0 + lr) * HH + k0 + lc + 4];
        aS[(lc + 0) * 65 + lr] = a0.x; aS[(lc + 1) * 65 + lr] = a0.y;
        aS[(lc + 2) * 65 + lr] = a0.z; aS[(lc + 3) * 65 + lr] = a0.w;
        aS[(lc + 4) * 65 + lr] = a1.x; aS[(lc + 5) * 65 + lr] = a1.y;
        aS[(lc + 6) * 65 + lr] = a1.z; aS[(lc + 7) * 65 + lr] = a1.w;
        bS[(lc + 0) * 65 + lr] = b0.x; bS[(lc + 1) * 65 + lr] = b0.y;
        bS[(lc + 2) * 65 + lr] = b0.z; bS[(lc + 3) * 65 + lr] = b0.w;
        bS[(lc + 4) * 65 + lr] = b1.x; bS[(lc + 5) * 65 + lr] = b1.y;
        bS[(lc + 6) * 65 + lr] = b1.z; bS[(lc + 7) * 65 + lr] = b1.w;
        __syncthreads();

        const int ty = t >> 4, tx = t & 15;
#pragma unroll
        for (int kk = 0; kk < 32; ++kk) {
            float a[4], bb[4];
#pragma unroll
            for (int u = 0; u < 4; ++u) { a[u] = aS[kk * 65 + ty * 4 + u]; bb[u] = bS[kk * 65 + tx * 4 + u]; }
#pragma unroll
            for (int u = 0; u < 4; ++u)
#pragma unroll
                for (int v = 0; v < 4; ++v) acc[u][v] += a[u] * bb[v];
        }
    }

    const int ty = t >> 4, tx = t & 15;
#pragma unroll
    for (int u = 0; u < 4; ++u) {
        float4 r;
        r.x = acc[u][0]; r.y = acc[u][1]; r.z = acc[u][2]; r.w = acc[u][3];
        *(float4*)&O[(size_t)(r0 + ty * 4 + u) * HH + c0 + tx * 4] = r;
    }
}

// ============ split fp32 -> fp16 hi + fp16 lo (elementwise) ==================
__global__ __launch_bounds__(256) void split_kernel(
    const float* __restrict__ in, __half* __restrict__ hi, __half* __restrict__ lo, int n4)
{
    int i = blockIdx.x * 256 + threadIdx.x;
    int stride = gridDim.x * 256;
    for (; i < n4; i += stride) {
        float4 x = ((const float4*)in)[i];
        __half hx = __float2half_rn(x.x), hy = __float2half_rn(x.y);
        __half hz = __float2half_rn(x.z), hw = __float2half_rn(x.w);
        __half lx = __float2half_rn(x.x - __half2float(hx));
        __half ly = __float2half_rn(x.y - __half2float(hy));
        __half lz = __float2half_rn(x.z - __half2float(hz));
        __half lw = __float2half_rn(x.w - __half2float(hw));
        ((__half2*)hi)[i * 2 + 0] = __halves2half2(hx, hy);
        ((__half2*)hi)[i * 2 + 1] = __halves2half2(hz, hw);
        ((__half2*)lo)[i * 2 + 0] = __halves2half2(lx, ly);
        ((__half2*)lo)[i * 2 + 1] = __halves2half2(lz, lw);
    }
}

// =================== v = latent[BS,64] @ Wv[64,64] ===========================
__global__ __launch_bounds__(256) void vproj_kernel(
    const float* __restrict__ X, const float* __restrict__ Wv, float* __restrict__ V)
{
    __shared__ float Ws[64 * 65];
    __shared__ float Xs[32 * 65];
    const int t  = threadIdx.x;
    const int r0 = blockIdx.x * 32;

#pragma unroll
    for (int u = 0; u < 16; ++u) {
        int idx = u * 256 + t; int r = idx >> 6, c = idx & 63;
        Ws[r * 65 + c] = Wv[idx];
    }
#pragma unroll
    for (int u = 0; u < 8; ++u) {
        int idx = u * 256 + t; int r = idx >> 6, c = idx & 63;
        Xs[r * 65 + c] = X[(size_t)(r0 + r) * 64 + c];
    }
    __syncthreads();

    const int row = t >> 3;
    const int c0  = (t & 7) * 8;
    float acc[8];
#pragma unroll
    for (int u = 0; u < 8; ++u) acc[u] = 0.f;
#pragma unroll 8
    for (int z = 0; z < 64; ++z) {
        float a = Xs[row * 65 + z];
#pragma unroll
        for (int u = 0; u < 8; ++u) acc[u] += a * Ws[z * 65 + c0 + u];
    }
#pragma unroll
    for (int u = 0; u < 8; ++u) V[(size_t)(r0 + row) * 64 + c0 + u] = acc[u];
}

// ============ transpose + split v: [b][s][d] fp32 -> [b][d][s] fp16 hi/lo ====
__global__ __launch_bounds__(256) void vtrans_kernel(
    const float* __restrict__ V, __half* __restrict__ vThi, __half* __restrict__ vTlo)
{
    __shared__ float s[64][65];
    const int t  = threadIdx.x;
    const int b  = blockIdx.y;
    const int s0 = blockIdx.x * 64;

#pragma unroll
    for (int i = 0; i < 4; ++i) {
        int flat = i * 256 + t;
        int r = flat >> 4, c = (flat & 15) * 4;
        float4 x = *(const float4*)&V[((size_t)b * SS + s0 + r) * ZZ + c];
        s[r][c] = x.x; s[r][c + 1] = x.y; s[r][c + 2] = x.z; s[r][c + 3] = x.w;
    }
    __syncthreads();

#pragma unroll
    for (int i = 0; i < 4; ++i) {
        int flat = i * 256 + t;
        int d = flat >> 4, sc = (flat & 15) * 4;
        __half h[4], l[4];
#pragma unroll
        for (int k = 0; k < 4; ++k) {
            float x = s[sc + k][d];
            h[k] = __float2half_rn(x);
            l[k] = __float2half_rn(x - __half2float(h[k]));
        }
        size_t o = ((size_t)b * ZZ + d) * SS + s0 + sc;
        *(__half2*)&vThi[o]     = __halves2half2(h[0], h[1]);
        *(__half2*)&vThi[o + 2] = __halves2half2(h[2], h[3]);
        *(__half2*)&vTlo[o]     = __halves2half2(l[0], l[1]);
        *(__half2*)&vTlo[o + 2] = __halves2half2(l[2], l[3]);
    }
}

// =========== Split-precision HMMA GEMM: C = A @ B^T, K=256 ===================
// CTA tile 128x128, 8 warps (2x4), warp tile 64x32, k-chunk 32, double buffer.
// IS_ALIGN=1: write p = exp(logit - tilemax) as fp16 + per-tile col max/sum
// IS_ALIGN=0: write split fp16 (qhi,qlo)
template<bool IS_ALIGN>
__global__ void __launch_bounds__(256, 2) mma_split_kernel(
    const __half* __restrict__ Ahig, const __half* __restrict__ Alog,
    const __half* __restrict__ Bhig, const __half* __restrict__ Blog,
    const void* __restrict__ mask, __half* __restrict__ Patt,
    __half* __restrict__ Qhi, __half* __restrict__ Qlo,
    float* __restrict__ Pmax, float* __restrict__ Psum)
{
    extern __shared__ __half sm[];
    const int t    = threadIdx.x;
    const int lane = t & 31;
    const int wid  = t >> 5;
    const int warpM = wid >> 2;
    const int warpN = wid & 3;
    const int b  = IS_ALIGN ? blockIdx.z : 0;
    const int m0 = blockIdx.y * 128;
    const int n0 = blockIdx.x * 128;

    const size_t arow = IS_ALIGN ? ((size_t)b * SS + m0) : (size_t)m0;
    const size_t brow = IS_ALIGN ? ((size_t)b * SS + n0) : (size_t)n0;
    const __half* Ah = Ahig + arow * HH;
    const __half* Al = Alog + arow * HH;
    const __half* Bh = Bhig + brow * HH;
    const __half* Bl = Blog + brow * HH;

    const uint32_t smbase = smem_u32(sm);

    float acc[4][4][4];
#pragma unroll
    for (int mt = 0; mt < 4; ++mt)
#pragma unroll
        for (int nt = 0; nt < 4; ++nt)
#pragma unroll
            for (int r = 0; r < 4; ++r) acc[mt][nt][r] = 0.f;

    auto issue = [&](int chunk, int p) {
#pragma unroll
        for (int i = 0; i < 8; ++i) {
            const __half* basep = (i < 2) ? Ah : (i < 4) ? Al : (i < 6) ? Bh : Bl;
            const int tile = i >> 1;
            const int flat = i * 256 + t;
            const int w = flat & 511;
            const int r = w >> 2, c16 = w & 3;
            const __half* g = basep + (size_t)r * HH + chunk * 32 + c16 * 8;
            const uint32_t d = smbase +
                (uint32_t)((p * 20480 + tile * 5120 + r * 40 + c16 * 8) * 2);
            asm volatile("cp.async.cg.shared.global [%0], [%1], 16;" :: "r"(d), "l"(g));
        }
        asm volatile("cp.async.commit_group;" ::: "memory");
    };

    issue(0, 0);

    const int aRow = warpM * 64 + (lane & 7) + ((lane >> 3) & 1) * 8;
    const int aK   = (lane >> 4) * 8;
    const int bRow = warpN * 32 + (lane & 7) + (lane >> 4) * 8;
    const int bK   = ((lane >> 3) & 1) * 8;

    for (int c = 0; c < 8; ++c) {
        asm volatile("cp.async.wait_group 0;" ::: "memory");
        __syncthreads();
        if (c < 7) issue(c + 1, (c + 1) & 1);

        const int p = c & 1;
        const uint32_t abase = smbase + (uint32_t)(p * 20480 * 2);
        const uint32_t bbase = abase + 10240 * 2;

#pragma unroll
        for (int k16 = 0; k16 < 32; k16 += 16) {
            uint32_t ah[4][4], al[4][4], bh[2][4], bl[2][4];
#pragma unroll
            for (int mt = 0; mt < 4; ++mt) {
                const uint32_t adr = abase +
                    (uint32_t)(((aRow + mt * 16) * 40 + k16 + aK) * 2);
                LDSM4(ah[mt], adr);
                LDSM4(al[mt], adr + 10240);
            }
#pragma unroll
            for (int ntp = 0; ntp < 2; ++ntp) {
                const uint32_t adr = bbase +
                    (uint32_t)(((bRow + ntp * 16) * 40 + k16 + bK) * 2);
                LDSM4(bh[ntp], adr);
                LDSM4(bl[ntp], adr + 10240);
            }
#pragma unroll
            for (int mt = 0; mt < 4; ++mt)
#pragma unroll
                for (int nt = 0; nt < 4; ++nt) {
                    const uint32_t bhf[2] = { bh[nt >> 1][(nt & 1) * 2],
                                              bh[nt >> 1][(nt & 1) * 2 + 1] };
                    const uint32_t blf[2] = { bl[nt >> 1][(nt & 1) * 2],
                                              bl[nt >> 1][(nt & 1) * 2 + 1] };
                    hmma16816(acc[mt][nt], ah[mt], bhf);
                    hmma16816(acc[mt][nt], ah[mt], blf);
                    hmma16816(acc[mt][nt], al[mt], bhf);
                }
        }
    }

    // ----------------------------- epilogue ---------------------------------
    if (IS_ALIGN) {
        const bool i32 = mask_is_i32(mask);
        const int*           mi = (const int*)mask;
        const unsigned char* mb = (const unsigned char*)mask;

        // mask + scale logits
#pragma unroll
        for (int mt = 0; mt < 4; ++mt) {
            const int i = m0 + warpM * 64 + mt * 16 + (lane >> 2);
            const bool k0 = i32 ? (mi[b * SS + i] != 0)     : (mb[b * SS + i] != 0);
            const bool k8 = i32 ? (mi[b * SS + i + 8] != 0) : (mb[b * SS + i + 8] != 0);
#pragma unroll
            for (int nt = 0; nt < 4; ++nt) {
                acc[mt][nt][0] = k0 ? acc[mt][nt][0] * INV_T : NEGINF;
                acc[mt][nt][1] = k0 ? acc[mt][nt][1] * INV_T : NEGINF;
                acc[mt][nt][2] = k8 ? acc[mt][nt][2] * INV_T : NEGINF;
                acc[mt][nt][3] = k8 ? acc[mt][nt][3] * INV_T : NEGINF;
            }
        }

        float* sMax = (float*)sm;          // [2][128]
        float* sSum = (float*)sm + 256;    // [2][128]
        __syncthreads();                   // mainloop smem reads done

        // tile max per column
#pragma unroll
        for (int nt = 0; nt < 4; ++nt)
#pragma unroll
            for (int pp = 0; pp < 2; ++pp) {
                float lm = -3.4e38f;
#pragma unroll
                for (int mt = 0; mt < 4; ++mt) {
                    lm = fmaxf(lm, acc[mt][nt][pp]);
                    lm = fmaxf(lm, acc[mt][nt][2 + pp]);
                }
#pragma unroll
                for (int o = 4; o < 32; o <<= 1)
                    lm = fmaxf(lm, __shfl_xor_sync(0xffffffffu, lm, o));
                const int cidx = warpN * 32 + nt * 8 + (lane & 3) * 2 + pp;
                if ((lane >> 2) == 0) sMax[warpM * 128 + cidx] = lm;
            }
        __syncthreads();

        // p = exp(x - tilemax), write fp16, accumulate column sums
        __half* pB = Patt + (size_t)b * SS * SS;
#pragma unroll
        for (int nt = 0; nt < 4; ++nt) {
            const int cidx0 = warpN * 32 + nt * 8 + (lane & 3) * 2;
            const float cmv0 = fmaxf(sMax[cidx0],     sMax[128 + cidx0]);
            const float cmv1 = fmaxf(sMax[cidx0 + 1], sMax[128 + cidx0 + 1]);
            float ls0 = 0.f, ls1 = 0.f;
#pragma unroll
            for (int mt = 0; mt < 4; ++mt) {
                const int i = m0 + warpM * 64 + mt * 16 + (lane >> 2);
                float p00 = fexp(acc[mt][nt][0] - cmv0);
                float p01 = fexp(acc[mt][nt][1] - cmv1);
                float p80 = fexp(acc[mt][nt][2] - cmv0);
                float p81 = fexp(acc[mt][nt][3] - cmv1);
                ls0 += p00 + p80;
                ls1 += p01 + p81;
                *(__half2*)&pB[(size_t)i * SS + n0 + cidx0] =
                    __halves2half2(__float2half_rn(p00), __float2half_rn(p01));
                *(__half2*)&pB[(size_t)(i + 8) * SS + n0 + cidx0] =
                    __halves2half2(__float2half_rn(p80), __float2half_rn(p81));
            }
#pragma unroll
            for (int o = 4; o < 32; o <<= 1) {
                ls0 += __shfl_xor_sync(0xffffffffu, ls0, o);
                ls1 += __shfl_xor_sync(0xffffffffu, ls1, o);
            }
            if ((lane >> 2) == 0) {
                sSum[warpM * 128 + cidx0]     = ls0;
                sSum[warpM * 128 + cidx0 + 1] = ls1;
            }
        }
        __syncthreads();

        if (warpM == 0 && (lane >> 2) == 0) {
#pragma unroll
            for (int nt = 0; nt < 4; ++nt)
#pragma unroll
                for (int pp = 0; pp < 2; ++pp) {
                    const int cidx = warpN * 32 + nt * 8 + (lane & 3) * 2 + pp;
                    const float cmv = fmaxf(sMax[cidx], sMax[128 + cidx]);
                    const float tot = sSum[cidx] + sSum[128 + cidx];
                    const size_t o = ((size_t)b * 16 + blockIdx.y) * SS + n0 + cidx;
                    Pmax[o] = cmv;
                    Psum[o] = tot;
                }
        }
    } else {
#pragma unroll
        for (int mt = 0; mt < 4; ++mt) {
            const size_t i = (size_t)m0 + warpM * 64 + mt * 16 + (lane >> 2);
#pragma unroll
            for (int nt = 0; nt < 4; ++nt) {
                const int n = n0 + warpN * 32 + nt * 8 + (lane & 3) * 2;
#pragma unroll
                for (int half = 0; half < 2; ++half) {
                    const size_t row = i + half * 8;
                    float x0 = acc[mt][nt][half * 2 + 0];
                    float x1 = acc[mt][nt][half * 2 + 1];
                    __half h0 = __float2half_rn(x0), h1 = __float2half_rn(x1);
                    __half l0 = __float2half_rn(x0 - __half2float(h0));
                    __half l1 = __float2half_rn(x1 - __half2float(h1));
                    *(__half2*)&Qhi[row * HH + n] = __halves2half2(h0, h1);
                    *(__half2*)&Qlo[row * HH + n] = __halves2half2(l0, l1);
                }
            }
        }
    }
}

// ===== combine per-tile partials into column stats (max, 1/sum) =============
__global__ __launch_bounds__(256) void combine_kernel(
    const float* __restrict__ Pmax, const float* __restrict__ Psum,
    float* __restrict__ cmax, float* __restrict__ rcs)
{
    const int idx = blockIdx.x * 256 + threadIdx.x;
    const int b = idx >> 11, j = idx & 2047;
    float pm[16];
#pragma unroll
    for (int tN = 0; tN < 16; ++tN)
        pm[tN] = Pmax[((size_t)b * 16 + tN) * SS + j];
    float m = pm[0];
#pragma unroll
    for (int tN = 1; tN < 16; ++tN) m = fmaxf(m, pm[tN]);
    float s = 0.f;
#pragma unroll
    for (int tN = 0; tN < 16; ++tN)
        s += Psum[((size_t)b * 16 + tN) * SS + j] * fexp(pm[tN] - m);
    cmax[idx] = m;
    rcs[idx]  = 1.0f / s;
}

// ===== attn = p * scale (write fp32) + output = attn @ v  (HMMA split) ======
// CTA: 128 i-rows (= one align i-tile) x full Z=64, loops over 32 j-chunks.
__global__ void __launch_bounds__(256, 2) fused_out_mma_kernel(
    const __half* __restrict__ patt, const __half* __restrict__ vThi,
    const __half* __restrict__ vTlo, const float* __restrict__ pmax,
    const float* __restrict__ cmax, const float* __restrict__ rcs,
    float* __restrict__ attOut, float* __restrict__ Out)
{
    extern __shared__ __half sm[];
    // halves: attnHi [128][72] @0, attnLo @9216, vHi [64][72] @18432, vLo @23040
    float* scaleS = (float*)(sm + 27648);   // [64]

    const int t    = threadIdx.x;
    const int lane = t & 31;
    const int wid  = t >> 5;
    const int warpM = wid >> 2;
    const int warpN = wid & 3;
    const int b    = blockIdx.y;
    const int tile = blockIdx.x;
    const int i0   = tile * 128;

    const __half* pB = patt + (size_t)b * SS * SS;
    float* aB = attOut + (size_t)b * SS * SS;
    const __half* vhB = vThi + (size_t)b * ZZ * SS;
    const __half* vlB = vTlo + (size_t)b * ZZ * SS;

    const uint32_t smb = smem_u32(sm);

    float acc[4][2][4];
#pragma unroll
    for (int mt = 0; mt < 4; ++mt)
#pragma unroll
        for (int nt = 0; nt < 2; ++nt)
#pragma unroll
            for (int r = 0; r < 4; ++r) acc[mt][nt][r] = 0.f;

    const int aRow = warpM * 64 + (lane & 7) + ((lane >> 3) & 1) * 8;
    const int aK   = (lane >> 4) * 8;
    const int bRow = warpN * 16 + (lane & 7) + (lane >> 4) * 8;
    const int bK   = ((lane >> 3) & 1) * 8;

    for (int jt = 0; jt < 32; ++jt) {
        const int j0 = jt * 64;
        __syncthreads();   // previous chunk's MMA reads done

        if (t < 64) {
            const int j = j0 + t;
            scaleS[t] = fexp(pmax[((size_t)b * 16 + tile) * SS + j]
                             - cmax[(size_t)b * SS + j]) * rcs[(size_t)b * SS + j];
        }

        // cp.async v^T tiles (64 d-rows x 64 j-cols, hi+lo)
#pragma unroll
        for (int i = 0; i < 2; ++i) {
            const int flat = i * 256 + t;
            const int r = flat >> 3, c = (flat & 7) * 8;
            const __half* gh = vhB + (size_t)r * SS + j0 + c;
            const __half* gl = vlB + (size_t)r * SS + j0 + c;
            const uint32_t dh = smb + (uint32_t)((18432 + r * 72 + c) * 2);
            const uint32_t dl = smb + (uint32_t)((23040 + r * 72 + c) * 2);
            asm volatile("cp.async.cg.shared.global [%0], [%1], 16;" :: "r"(dh), "l"(gh));
            asm volatile("cp.async.cg.shared.global [%0], [%1], 16;" :: "r"(dl), "l"(gl));
        }
        asm volatile("cp.async.commit_group;" ::: "memory");
        __syncthreads();   // scaleS visible

        // attn = p * scale: LDG p fp16, write fp32 attn, split to smem hi/lo
#pragma unroll
        for (int u = 0; u < 4; ++u) {
            const int flat = u * 256 + t;
            const int r = flat >> 3, c = (flat & 7) * 8;
            const __half2* src = (const __half2*)&pB[(size_t)(i0 + r) * SS + j0 + c];
            __half2 p01 = src[0], p23 = src[1], p45 = src[2], p67 = src[3];
            float2 f0 = __half22float2(p01), f1 = __half22float2(p23);
            float2 f2 = __half22float2(p45), f3 = __half22float2(p67);
            float a0 = f0.x * scaleS[c + 0], a1 = f0.y * scaleS[c + 1];
            float a2 = f1.x * scaleS[c + 2], a3 = f1.y * scaleS[c + 3];
            float a4 = f2.x * scaleS[c + 4], a5 = f2.y * scaleS[c + 5];
            float a6 = f3.x * scaleS[c + 6], a7 = f3.y * scaleS[c + 7];
            float4 w0, w1;
            w0.x = a0; w0.y = a1; w0.z = a2; w0.w = a3;
            w1.x = a4; w1.y = a5; w1.z = a6; w1.w = a7;
            *(float4*)&aB[(size_t)(i0 + r) * SS + j0 + c]     = w0;
            *(float4*)&aB[(size_t)(i0 + r) * SS + j0 + c + 4] = w1;

            __half h[8], l[8];
            h[0] = __float2half_rn(a0); l[0] = __float2half_rn(a0 - __half2float(h[0]));
            h[1] = __float2half_rn(a1); l[1] = __float2half_rn(a1 - __half2float(h[1]));
            h[2] = __float2half_rn(a2); l[2] = __float2half_rn(a2 - __half2float(h[2]));
            h[3] = __float2half_rn(a3); l[3] = __float2half_rn(a3 - __half2float(h[3]));
            h[4] = __float2half_rn(a4); l[4] = __float2half_rn(a4 - __half2float(h[4]));
            h[5] = __float2half_rn(a5); l[5] = __float2half_rn(a5 - __half2float(h[5]));
            h[6] = __float2half_rn(a6); l[6] = __float2half_rn(a6 - __half2float(h[6]));
            h[7] = __float2half_rn(a7); l[7] = __float2half_rn(a7 - __half2float(h[7]));
            __half2* ph = (__half2*)&sm[r * 72 + c];
            ph[0] = __halves2half2(h[0], h[1]); ph[1] = __halves2half2(h[2], h[3]);
            ph[2] = __halves2half2(h[4], h[5]); ph[3] = __halves2half2(h[6], h[7]);
            __half2* pl = (__half2*)&sm[9216 + r * 72 + c];
            pl[0] = __halves2half2(l[0], l[1]); pl[1] = __halves2half2(l[2], l[3]);
            pl[2] = __halves2half2(l[4], l[5]); pl[3] = __halves2half2(l[6], l[7]);
        }
        asm volatile("cp.async.wait_group 0;" ::: "memory");
        __syncthreads();

        // MMA: M128 x N64 x K64 (attn hi/lo x v hi/lo, 3 terms)
#pragma unroll
        for (int k16 = 0; k16 < 64; k16 += 16) {
            uint32_t ah[4][4], al[4][4], bh[4], bl[4];
#pragma unroll
            for (int mt = 0; mt < 4; ++mt) {
                const uint32_t adr = smb +
                    (uint32_t)(((aRow + mt * 16) * 72 + k16 + aK) * 2);
                LDSM4(ah[mt], adr);
                LDSM4(al[mt], adr + 9216 * 2);
            }
            const uint32_t badr = smb +
                (uint32_t)((18432 + bRow * 72 + k16 + bK) * 2);
            LDSM4(bh, badr);
            LDSM4(bl, badr + 4608 * 2);
#pragma unroll
            for (int mt = 0; mt < 4; ++mt)
#pragma unroll
                for (int nt = 0; nt < 2; ++nt) {
                    const uint32_t bhf[2] = { bh[nt * 2], bh[nt * 2 + 1] };
                    const uint32_t blf[2] = { bl[nt * 2], bl[nt * 2 + 1] };
                    hmma16816(acc[mt][nt], ah[mt], bhf);
                    hmma16816(acc[mt][nt], ah[mt], blf);
                    hmma16816(acc[mt][nt], al[mt], bhf);
                }
        }
    }

    // epilogue: Out[b][i][d]
#pragma unroll
    for (int mt = 0; mt < 4; ++mt) {
        const int i = i0 + warpM * 64 + mt * 16 + (lane >> 2);
#pragma unroll
        for (int nt = 0; nt < 2; ++nt) {
            const int d = warpN * 16 + nt * 8 + (lane & 3) * 2;
            float2 v0, v8;
            v0.x = acc[mt][nt][0]; v0.y = acc[mt][nt][1];
            v8.x = acc[mt][nt][2]; v8.y = acc[mt][nt][3];
            *(float2*)&Out[((size_t)b * SS + i) * ZZ + d]     = v0;
            *(float2*)&Out[((size_t)b * SS + i + 8) * ZZ + d] = v8;
        }
    }
}

// ============================== launch ======================================
extern "C" void kernel_launch(void* const* d_in, const int* in_sizes, int n_in,
                              void* d_out, int out_size)
{
    const float* enc  = (const float*)d_in[0];
    const float* dec  = (const float*)d_in[1];
    const float* lat  = (const float*)d_in[3];
    const void*  mask = d_in[4];
    const float* Wq   = (const float*)d_in[5];
    const float* Wk   = (const float*)d_in[6];
    const float* Wv   = (const float*)d_in[7];

    float* outp = (float*)d_out;

    const size_t OUTE = (size_t)BB * SS * ZZ;
    const size_t ATTE = (size_t)BB * SS * SS;

    float  *GTp, *vp, *cmaxp, *rcsp, *pmaxp, *psump, *attfb;
    __half *GThi, *GTlo, *dhi, *dlo, *ehi, *elo, *qhi, *qlo, *vthi, *vtlo, *pattp;
    cudaGetSymbolAddress((void**)&GTp,   g_GT);
    cudaGetSymbolAddress((void**)&GThi,  g_GThi);
    cudaGetSymbolAddress((void**)&GTlo,  g_GTlo);
    cudaGetSymbolAddress((void**)&dhi,   g_dechi);
    cudaGetSymbolAddress((void**)&dlo,   g_declo);
    cudaGetSymbolAddress((void**)&ehi,   g_ehi);
    cudaGetSymbolAddress((void**)&elo,   g_elo);
    cudaGetSymbolAddress((void**)&qhi,   g_qhi);
    cudaGetSymbolAddress((void**)&qlo,   g_qlo);
    cudaGetSymbolAddress((void**)&vp,    g_v);
    cudaGetSymbolAddress((void**)&vthi,  g_vThi);
    cudaGetSymbolAddress((void**)&vtlo,  g_vTlo);
    cudaGetSymbolAddress((void**)&pattp, g_patt);
    cudaGetSymbolAddress((void**)&pmaxp, g_pmax);
    cudaGetSymbolAddress((void**)&psump, g_psum);
    cudaGetSymbolAddress((void**)&cmaxp, g_cmax);
    cudaGetSymbolAddress((void**)&rcsp,  g_rcs);
    cudaGetSymbolAddress((void**)&attfb, g_att);

    float* attnbuf = ((size_t)out_size >= OUTE + ATTE) ? (outp + OUTE) : attfb;

    const int M = BB * SS;   // 65536

    static int smem_set = 0;
    if (!smem_set) {
        cudaFuncSetAttribute(mma_split_kernel<true>,
                             cudaFuncAttributeMaxDynamicSharedMemorySize, 81920);
        cudaFuncSetAttribute(mma_split_kernel<false>,
                             cudaFuncAttributeMaxDynamicSharedMemorySize, 81920);
        cudaFuncSetAttribute(fused_out_mma_kernel,
                             cudaFuncAttributeMaxDynamicSharedMemorySize, 56320);
        smem_set = 1;
    }

    gmat_kernel<<<dim3(4, 4), 256>>>(Wk, Wq, GTp);
    split_kernel<<<64, 256>>>(GTp, GThi, GTlo, HH * HH / 4);
    split_kernel<<<592, 256>>>(dec, dhi, dlo, M * HH / 4);
    split_kernel<<<592, 256>>>(enc, ehi, elo, M * HH / 4);
    vproj_kernel<<<M / 32, 256>>>(lat, Wv, vp);
    vtrans_kernel<<<dim3(SS / 64, BB), 256>>>(vp, vthi, vtlo);

    mma_split_kernel<false><<<dim3(HH / 128, M / 128, 1), 256, 81920>>>(
        dhi, dlo, GThi, GTlo, nullptr, nullptr, qhi, qlo, nullptr, nullptr);

    mma_split_kernel<true><<<dim3(SS / 128, SS / 128, BB), 256, 81920>>>(
        qhi, qlo, ehi, elo, mask, pattp, nullptr, nullptr, pmaxp, psump);

    combine_kernel<<<(BB * SS) / 256, 256>>>(pmaxp, psump, cmaxp, rcsp);

    fused_out_mma_kernel<<<dim3(SS / 128, BB), 256, 56320>>>(
        pattp, vthi, vtlo, pmaxp, cmaxp, rcsp, attnbuf, outp);
}